// round 3
// baseline (speedup 1.0000x reference)
#include <cuda_runtime.h>
#include <cstdint>

#define NP1   100001
#define BATCH 1024
#define SEQ   50
#define LBASK 20
#define HID   128

__device__ float g_X [SEQ * BATCH * HID];
__device__ float g_ys[SEQ * BATCH * HID];
__device__ float g_hidden[BATCH * 64];

__device__ __forceinline__ float tf32r(float f) {
    uint32_t u; asm("cvt.rna.tf32.f32 %0, %1;" : "=r"(u) : "f"(f));
    return __uint_as_float(u);
}
__device__ __forceinline__ float sigf(float x)  { return 1.0f / (1.0f + __expf(-x)); }
__device__ __forceinline__ float tanh_(float x) { return 2.0f / (1.0f + __expf(-2.0f * x)) - 1.0f; }

__device__ __forceinline__ void mma_tf32(float d[4], float a0, float a1, float a2, float a3,
                                         float b0, float b1) {
    asm volatile(
        "mma.sync.aligned.m16n8k8.row.col.f32.tf32.tf32.f32 "
        "{%0,%1,%2,%3},{%4,%5,%6,%7},{%8,%9},{%0,%1,%2,%3};"
        : "+f"(d[0]), "+f"(d[1]), "+f"(d[2]), "+f"(d[3])
        : "r"(__float_as_uint(a0)), "r"(__float_as_uint(a1)),
          "r"(__float_as_uint(a2)), "r"(__float_as_uint(a3)),
          "r"(__float_as_uint(b0)), "r"(__float_as_uint(b1)));
}
__device__ __forceinline__ uint32_t smem_u32(const void* p) {
    uint32_t a;
    asm("{ .reg .u64 t; cvta.to.shared.u64 t, %1; cvt.u32.u64 %0, t; }" : "=r"(a) : "l"(p));
    return a;
}
__device__ __forceinline__ void cluster_sync_() {
    asm volatile("barrier.cluster.arrive.aligned;\n\tbarrier.cluster.wait.aligned;" ::: "memory");
}

// ============ Kernel 1: featurize -> g_X[s][b][128] ============
__global__ void __launch_bounds__(256)
featurize_kernel(const int* __restrict__ prod, const int* __restrict__ cat,
                 const float* __restrict__ age, const float* __restrict__ tsv,
                 const float* __restrict__ gender,
                 const float* __restrict__ emb_p, const float* __restrict__ emb_c,
                 const float* __restrict__ W_ts, const float* __restrict__ b_ts,
                 const float* __restrict__ W_uf, const float* __restrict__ b_uf) {
    int gid = blockIdx.x * 8 + (threadIdx.x >> 5);
    if (gid >= BATCH * SEQ) return;
    int lane = threadIdx.x & 31;
    int b = gid / SEQ, s = gid % SEQ;
    const int* pp = prod + gid * LBASK;
    const int* cc = cat  + gid * LBASK;
    float2 pa = make_float2(0.f, 0.f);
    float  ca = 0.f;
#pragma unroll 4
    for (int l = 0; l < LBASK; l++) {
        float2 v = *reinterpret_cast<const float2*>(emb_p + (size_t)pp[l] * 64 + lane * 2);
        pa.x += v.x; pa.y += v.y;
        ca += emb_c[cc[l] * 32 + lane];
    }
    float* xr = g_X + ((size_t)s * BATCH + b) * HID;
    pa.x *= (1.f / LBASK); pa.y *= (1.f / LBASK);
    *reinterpret_cast<float2*>(xr + lane * 2) = pa;
    xr[64 + lane] = ca * (1.f / LBASK);
    if (lane < 16) {
        xr[96 + lane] = W_ts[lane] * tsv[b * SEQ + s] + b_ts[lane];
    } else {
        int j = lane - 16;
        xr[112 + j] = W_uf[2 * j] * age[b] + W_uf[2 * j + 1] * gender[b] + b_uf[j];
    }
}

// ============ Kernel 2: 2-layer LSTM, cluster(4) per 32-batch tile ============
#define WS_STRIDE 260
#define GS_STRIDE 132
#define CS_STRIDE 33
#define OFF_W    0
#define OFF_XH0  (128 * WS_STRIDE)
#define OFF_XH1  (OFF_XH0 + 32 * WS_STRIDE)
#define OFF_GATE (OFF_XH1 + 32 * WS_STRIDE)
#define OFF_C    (OFF_GATE + 32 * GS_STRIDE)
#define OFF_BIAS (OFF_C + 32 * CS_STRIDE)
#define SMEM_FLOATS (OFF_BIAS + 128)
#define LSTM_SMEM_BYTES (SMEM_FLOATS * 4)

__device__ __forceinline__ void load_x_tile(float* dst, const float* Xsrc, int s, int b0, int t) {
    const float4* src = reinterpret_cast<const float4*>(Xsrc + ((size_t)s * BATCH + b0) * HID);
#pragma unroll
    for (int ii = 0; ii < 8; ii++) {
        int i = t + ii * 128;
        float4 v = src[i];
        float* d = dst + (i >> 5) * WS_STRIDE + (i & 31) * 4;
        d[0] = tf32r(v.x); d[1] = tf32r(v.y); d[2] = tf32r(v.z); d[3] = tf32r(v.w);
    }
}

__global__ void __launch_bounds__(128, 1) __cluster_dims__(4, 1, 1)
lstm_kernel(const float* __restrict__ Wih0, const float* __restrict__ Whh0,
            const float* __restrict__ bih0, const float* __restrict__ bhh0,
            const float* __restrict__ Wih1, const float* __restrict__ Whh1,
            const float* __restrict__ bih1, const float* __restrict__ bhh1,
            const float* __restrict__ W1, const float* __restrict__ b1) {
    extern __shared__ float sm[];
    float* W_s     = sm + OFF_W;
    float* xhbuf0  = sm + OFF_XH0;
    float* xhbuf1  = sm + OFF_XH1;
    float* gates_s = sm + OFF_GATE;
    float* c_s     = sm + OFF_C;
    float* bias_s  = sm + OFF_BIAS;

    int t = threadIdx.x;
    int warp = t >> 5, lane = t & 31, g = lane >> 2, q = lane & 3;
    uint32_t r; asm("mov.u32 %0, %%cluster_ctarank;" : "=r"(r));
    int b0 = (blockIdx.x >> 2) * 32;

    for (int layer = 0; layer < 2; layer++) {
        const float* Wih = layer ? Wih1 : Wih0;
        const float* Whh = layer ? Whh1 : Whh0;
        const float* bih = layer ? bih1 : bih0;
        const float* bhh = layer ? bhh1 : bhh0;
        const float* Xsrc = layer ? g_ys : g_X;

        { // weight slice: local row n -> global row (n>>5)*128 + 32r + (n&31)
            int n = t;
            int grow = (n >> 5) * HID + 32 * (int)r + (n & 31);
            const float4* wi = reinterpret_cast<const float4*>(Wih + (size_t)grow * HID);
            const float4* wh = reinterpret_cast<const float4*>(Whh + (size_t)grow * HID);
            float* dst = W_s + n * WS_STRIDE;
#pragma unroll 8
            for (int k4 = 0; k4 < 32; k4++) {
                float4 v = wi[k4];
                dst[k4*4+0] = tf32r(v.x); dst[k4*4+1] = tf32r(v.y);
                dst[k4*4+2] = tf32r(v.z); dst[k4*4+3] = tf32r(v.w);
                float4 w = wh[k4];
                dst[128+k4*4+0] = tf32r(w.x); dst[128+k4*4+1] = tf32r(w.y);
                dst[128+k4*4+2] = tf32r(w.z); dst[128+k4*4+3] = tf32r(w.w);
            }
            bias_s[n] = bih[grow] + bhh[grow];
        }
        for (int i = t; i < 32 * CS_STRIDE; i += 128) c_s[i] = 0.f;
        for (int i = t; i < 4096; i += 128)
            xhbuf0[(i >> 7) * WS_STRIDE + 128 + (i & 127)] = 0.f;
        load_x_tile(xhbuf0, Xsrc, 0, b0, t);
        __syncthreads();
        cluster_sync_();

        int cur = 0;
        for (int s = 0; s < SEQ; s++) {
            float* A  = cur ? xhbuf1 : xhbuf0;
            float* Bn = cur ? xhbuf0 : xhbuf1;
            if (s + 1 < SEQ) load_x_tile(Bn, Xsrc, s + 1, b0, t);

            float acc[2][4][4];
#pragma unroll
            for (int mt = 0; mt < 2; mt++)
#pragma unroll
                for (int nt = 0; nt < 4; nt++)
#pragma unroll
                    for (int e = 0; e < 4; e++) acc[mt][nt][e] = 0.f;

            const float* Wb = W_s + (warp * 32) * WS_STRIDE;
#pragma unroll 4
            for (int kt = 0; kt < 32; kt++) {
                int k0 = kt * 8;
                float a[2][4];
#pragma unroll
                for (int mt = 0; mt < 2; mt++) {
                    const float* Ar = A + (mt * 16 + g) * WS_STRIDE + k0 + q;
                    a[mt][0] = Ar[0];
                    a[mt][2] = Ar[4];
                    a[mt][1] = Ar[8 * WS_STRIDE];
                    a[mt][3] = Ar[8 * WS_STRIDE + 4];
                }
#pragma unroll
                for (int nt = 0; nt < 4; nt++) {
                    const float* Br = Wb + (nt * 8 + g) * WS_STRIDE + k0 + q;
                    float bv0 = Br[0], bv1 = Br[4];
                    mma_tf32(acc[0][nt], a[0][0], a[0][1], a[0][2], a[0][3], bv0, bv1);
                    mma_tf32(acc[1][nt], a[1][0], a[1][1], a[1][2], a[1][3], bv0, bv1);
                }
            }
#pragma unroll
            for (int mt = 0; mt < 2; mt++)
#pragma unroll
                for (int nt = 0; nt < 4; nt++) {
                    int n = warp * 32 + nt * 8 + 2 * q;
                    int m = mt * 16 + g;
                    gates_s[m * GS_STRIDE + n]           = acc[mt][nt][0];
                    gates_s[m * GS_STRIDE + n + 1]       = acc[mt][nt][1];
                    gates_s[(m + 8) * GS_STRIDE + n]     = acc[mt][nt][2];
                    gates_s[(m + 8) * GS_STRIDE + n + 1] = acc[mt][nt][3];
                }
            __syncthreads();

            { // cell update: thread t -> batch m = t>>2, units ub..ub+7 (local)
                int m = t >> 2, ub = (t & 3) * 8;
                uint32_t bn_sh = smem_u32(Bn);
                uint32_t peer[4];
#pragma unroll
                for (int rr = 0; rr < 4; rr++)
                    asm("mapa.shared::cluster.u32 %0, %1, %2;"
                        : "=r"(peer[rr]) : "r"(bn_sh), "r"((uint32_t)rr));
                float hv[8];
#pragma unroll
                for (int j = 0; j < 8; j++) {
                    int ul = ub + j;
                    float ip = gates_s[m * GS_STRIDE + ul]      + bias_s[ul];
                    float fp = gates_s[m * GS_STRIDE + 32 + ul] + bias_s[32 + ul];
                    float gp = gates_s[m * GS_STRIDE + 64 + ul] + bias_s[64 + ul];
                    float op = gates_s[m * GS_STRIDE + 96 + ul] + bias_s[96 + ul];
                    float c = sigf(fp) * c_s[m * CS_STRIDE + ul] + sigf(ip) * tanh_(gp);
                    c_s[m * CS_STRIDE + ul] = c;
                    hv[j] = tf32r(sigf(op) * tanh_(c));
                }
                int u0 = 32 * (int)r + ub;
                uint32_t off = (uint32_t)((m * WS_STRIDE + 128 + u0) * 4);
                uint64_t hp[4];
#pragma unroll
                for (int j = 0; j < 4; j++) {
                    uint2 p = make_uint2(__float_as_uint(hv[2*j]), __float_as_uint(hv[2*j+1]));
                    hp[j] = ((uint64_t)p.y << 32) | p.x;
                }
#pragma unroll
                for (int rr = 0; rr < 4; rr++) {
                    uint32_t base = peer[rr] + off;
#pragma unroll
                    for (int j = 0; j < 4; j++)
                        asm volatile("st.shared::cluster.b64 [%0], %1;"
                                     :: "r"(base + 8u * j), "l"(hp[j]));
                }
                if (layer == 0) {
                    float* yr = g_ys + ((size_t)s * BATCH + b0 + m) * HID + u0;
#pragma unroll
                    for (int j = 0; j < 8; j++) yr[j] = hv[j];
                }
            }
            cluster_sync_();
            cur ^= 1;
        }

        if (layer == 1) { // fused: hidden = relu(h_last @ W1^T + b1)
            float* A = cur ? xhbuf1 : xhbuf0;
            for (int idx = t; idx < 512; idx += 128) {
                int m = idx >> 4, jj = idx & 15;
                int row = 16 * (int)r + jj;
                const float* w = W1 + row * HID;
                const float* h = A + m * WS_STRIDE + 128;
                float sum = b1[row];
#pragma unroll 8
                for (int k = 0; k < HID; k++) sum += w[k] * h[k];
                g_hidden[(b0 + m) * 64 + row] = fmaxf(sum, 0.f);
            }
        }
        __syncthreads();
        cluster_sync_();
    }
}

// ============ Kernel 3: head  out[1024,NP1] = g_hidden @ W2^T + b2 ============
#define HD_STRIDE 68
#define HEAD_SMEM_BYTES (2 * 128 * HD_STRIDE * 4)

__global__ void __launch_bounds__(256)
head_kernel(const float* __restrict__ W2, const float* __restrict__ b2,
            float* __restrict__ out) {
    extern __shared__ float sm[];
    float* As = sm;
    float* Bs = sm + 128 * HD_STRIDE;
    int t = threadIdx.x;
    int n0 = blockIdx.x * 128, m0 = blockIdx.y * 128;

    {
        const float4* src = reinterpret_cast<const float4*>(g_hidden + (size_t)m0 * 64);
#pragma unroll
        for (int ii = 0; ii < 8; ii++) {
            int i = t + ii * 256;
            float4 v = src[i];
            float* d = As + (i >> 4) * HD_STRIDE + (i & 15) * 4;
            d[0] = tf32r(v.x); d[1] = tf32r(v.y); d[2] = tf32r(v.z); d[3] = tf32r(v.w);
        }
#pragma unroll
        for (int ii = 0; ii < 8; ii++) {
            int i = t + ii * 256;
            int rn = i >> 4;
            float4 v = make_float4(0.f, 0.f, 0.f, 0.f);
            if (n0 + rn < NP1)
                v = reinterpret_cast<const float4*>(W2 + (size_t)(n0 + rn) * 64)[i & 15];
            float* d = Bs + rn * HD_STRIDE + (i & 15) * 4;
            d[0] = tf32r(v.x); d[1] = tf32r(v.y); d[2] = tf32r(v.z); d[3] = tf32r(v.w);
        }
    }
    __syncthreads();

    int warp = t >> 5, lane = t & 31, g = lane >> 2, q = lane & 3;
    int wm = (warp >> 2) * 64, wn = (warp & 3) * 32;

    float acc[4][4][4];
#pragma unroll
    for (int mt = 0; mt < 4; mt++)
#pragma unroll
        for (int nt = 0; nt < 4; nt++)
#pragma unroll
            for (int e = 0; e < 4; e++) acc[mt][nt][e] = 0.f;

#pragma unroll
    for (int kt = 0; kt < 8; kt++) {
        int k0 = kt * 8;
        float a[4][4];
#pragma unroll
        for (int mt = 0; mt < 4; mt++) {
            const float* Ar = As + (wm + mt * 16 + g) * HD_STRIDE + k0 + q;
            a[mt][0] = Ar[0];
            a[mt][2] = Ar[4];
            a[mt][1] = Ar[8 * HD_STRIDE];
            a[mt][3] = Ar[8 * HD_STRIDE + 4];
        }
#pragma unroll
        for (int nt = 0; nt < 4; nt++) {
            const float* Br = Bs + (wn + nt * 8 + g) * HD_STRIDE + k0 + q;
            float bv0 = Br[0], bv1 = Br[4];
#pragma unroll
            for (int mt = 0; mt < 4; mt++)
                mma_tf32(acc[mt][nt], a[mt][0], a[mt][1], a[mt][2], a[mt][3], bv0, bv1);
        }
    }

#pragma unroll
    for (int mt = 0; mt < 4; mt++)
#pragma unroll
        for (int nt = 0; nt < 4; nt++) {
            int mg = m0 + wm + mt * 16 + g;
            int ng = n0 + wn + nt * 8 + 2 * q;
            if (ng < NP1) {
                float bb = b2[ng];
                out[(size_t)mg * NP1 + ng]       = acc[mt][nt][0] + bb;
                out[(size_t)(mg + 8) * NP1 + ng] = acc[mt][nt][2] + bb;
            }
            if (ng + 1 < NP1) {
                float bb = b2[ng + 1];
                out[(size_t)mg * NP1 + ng + 1]       = acc[mt][nt][1] + bb;
                out[(size_t)(mg + 8) * NP1 + ng + 1] = acc[mt][nt][3] + bb;
            }
        }
}

// ============ launch ============
extern "C" void kernel_launch(void* const* d_in, const int* in_sizes, int n_in,
                              void* d_out, int out_size) {
    const int*   prod   = (const int*)d_in[0];
    const int*   cat    = (const int*)d_in[1];
    const float* age    = (const float*)d_in[2];
    const float* tsv    = (const float*)d_in[3];
    const float* gender = (const float*)d_in[4];
    const float* emb_p  = (const float*)d_in[5];
    const float* emb_c  = (const float*)d_in[6];
    const float* W_ts   = (const float*)d_in[7];
    const float* b_ts   = (const float*)d_in[8];
    const float* W_uf   = (const float*)d_in[9];
    const float* b_uf   = (const float*)d_in[10];
    const float* Wih0   = (const float*)d_in[11];
    const float* Whh0   = (const float*)d_in[12];
    const float* bih0   = (const float*)d_in[13];
    const float* bhh0   = (const float*)d_in[14];
    const float* Wih1   = (const float*)d_in[15];
    const float* Whh1   = (const float*)d_in[16];
    const float* bih1   = (const float*)d_in[17];
    const float* bhh1   = (const float*)d_in[18];
    const float* W1     = (const float*)d_in[19];
    const float* b1     = (const float*)d_in[20];
    const float* W2     = (const float*)d_in[21];
    const float* b2     = (const float*)d_in[22];
    float* out = (float*)d_out;

    cudaFuncSetAttribute(lstm_kernel, cudaFuncAttributeMaxDynamicSharedMemorySize, LSTM_SMEM_BYTES);
    cudaFuncSetAttribute(head_kernel, cudaFuncAttributeMaxDynamicSharedMemorySize, HEAD_SMEM_BYTES);

    featurize_kernel<<<(BATCH * SEQ + 7) / 8, 256>>>(prod, cat, age, tsv, gender,
                                                     emb_p, emb_c, W_ts, b_ts, W_uf, b_uf);
    lstm_kernel<<<(BATCH / 32) * 4, 128, LSTM_SMEM_BYTES>>>(Wih0, Whh0, bih0, bhh0,
                                                            Wih1, Whh1, bih1, bhh1, W1, b1);
    head_kernel<<<dim3((NP1 + 127) / 128, BATCH / 128), 256, HEAD_SMEM_BYTES>>>(W2, b2, out);
}

// round 4
// speedup vs baseline: 1.1012x; 1.1012x over previous
#include <cuda_runtime.h>
#include <cstdint>

#define NP1   100001
#define BATCH 1024
#define SEQ   50
#define LBASK 20
#define HID   128

__device__ float g_X    [SEQ * BATCH * HID];
__device__ float g_gates[SEQ * BATCH * 4 * HID];   // 105 MB, reused per layer
__device__ float g_ys   [SEQ * BATCH * HID];
__device__ float g_hidden[BATCH * 64];

__device__ __forceinline__ float tf32r(float f) {
    uint32_t u; asm("cvt.rna.tf32.f32 %0, %1;" : "=r"(u) : "f"(f));
    return __uint_as_float(u);
}
__device__ __forceinline__ float sigf(float x)  { return 1.0f / (1.0f + __expf(-x)); }
__device__ __forceinline__ float tanh_(float x) { return 2.0f / (1.0f + __expf(-2.0f * x)) - 1.0f; }

__device__ __forceinline__ void mma_tf32(float d[4], float a0, float a1, float a2, float a3,
                                         float b0, float b1) {
    asm volatile(
        "mma.sync.aligned.m16n8k8.row.col.f32.tf32.tf32.f32 "
        "{%0,%1,%2,%3},{%4,%5,%6,%7},{%8,%9},{%0,%1,%2,%3};"
        : "+f"(d[0]), "+f"(d[1]), "+f"(d[2]), "+f"(d[3])
        : "r"(__float_as_uint(a0)), "r"(__float_as_uint(a1)),
          "r"(__float_as_uint(a2)), "r"(__float_as_uint(a3)),
          "r"(__float_as_uint(b0)), "r"(__float_as_uint(b1)));
}
__device__ __forceinline__ uint32_t smem_u32(const void* p) {
    uint32_t a;
    asm("{ .reg .u64 t; cvta.to.shared.u64 t, %1; cvt.u32.u64 %0, t; }" : "=r"(a) : "l"(p));
    return a;
}
__device__ __forceinline__ void cluster_sync_() {
    asm volatile("barrier.cluster.arrive.aligned;\n\tbarrier.cluster.wait.aligned;" ::: "memory");
}

// ==================== Kernel 1: featurize -> g_X[s][b][128] ====================
__global__ void __launch_bounds__(256)
featurize_kernel(const int* __restrict__ prod, const int* __restrict__ cat,
                 const float* __restrict__ age, const float* __restrict__ tsv,
                 const float* __restrict__ gender,
                 const float* __restrict__ emb_p, const float* __restrict__ emb_c,
                 const float* __restrict__ W_ts, const float* __restrict__ b_ts,
                 const float* __restrict__ W_uf, const float* __restrict__ b_uf) {
    int gid = blockIdx.x * 8 + (threadIdx.x >> 5);
    if (gid >= BATCH * SEQ) return;
    int lane = threadIdx.x & 31;
    int b = gid / SEQ, s = gid % SEQ;
    const int* pp = prod + gid * LBASK;
    const int* cc = cat  + gid * LBASK;
    float2 pa = make_float2(0.f, 0.f);
    float  ca = 0.f;
#pragma unroll 4
    for (int l = 0; l < LBASK; l++) {
        float2 v = *reinterpret_cast<const float2*>(emb_p + (size_t)pp[l] * 64 + lane * 2);
        pa.x += v.x; pa.y += v.y;
        ca += emb_c[cc[l] * 32 + lane];
    }
    float* xr = g_X + ((size_t)s * BATCH + b) * HID;
    pa.x *= (1.f / LBASK); pa.y *= (1.f / LBASK);
    *reinterpret_cast<float2*>(xr + lane * 2) = pa;
    xr[64 + lane] = ca * (1.f / LBASK);
    if (lane < 16) {
        xr[96 + lane] = W_ts[lane] * tsv[b * SEQ + s] + b_ts[lane];
    } else {
        int j = lane - 16;
        xr[112 + j] = W_uf[2 * j] * age[b] + W_uf[2 * j + 1] * gender[b] + b_uf[j];
    }
}

// ==================== Kernel 2: bulk ih-GEMM ====================
// g_gates[M=51200][512] = X[M][128] @ Wih^T + (bih + bhh)
#define BK_STRIDE 132
#define BULK_SMEM_BYTES (2 * 128 * BK_STRIDE * 4)

__global__ void __launch_bounds__(256)
bulk_gemm_kernel(const float* __restrict__ X, const float* __restrict__ Wih,
                 const float* __restrict__ bih, const float* __restrict__ bhh,
                 float* __restrict__ out) {
    extern __shared__ float sm[];
    float* As = sm;
    float* Bs = sm + 128 * BK_STRIDE;
    int t = threadIdx.x;
    int n0 = blockIdx.x * 128;
    int m0 = blockIdx.y * 128;

    { // load tiles (tf32 rounded)
        const float4* xs = reinterpret_cast<const float4*>(X + (size_t)m0 * HID);
        const float4* ws = reinterpret_cast<const float4*>(Wih + (size_t)n0 * HID);
#pragma unroll
        for (int ii = 0; ii < 16; ii++) {
            int i = t + ii * 256;               // 4096 float4s
            float4 v = xs[i];
            float* d = As + (i >> 5) * BK_STRIDE + (i & 31) * 4;
            d[0] = tf32r(v.x); d[1] = tf32r(v.y); d[2] = tf32r(v.z); d[3] = tf32r(v.w);
            float4 w = ws[i];
            float* e = Bs + (i >> 5) * BK_STRIDE + (i & 31) * 4;
            e[0] = tf32r(w.x); e[1] = tf32r(w.y); e[2] = tf32r(w.z); e[3] = tf32r(w.w);
        }
    }
    __syncthreads();

    int warp = t >> 5, lane = t & 31, g = lane >> 2, q = lane & 3;
    int wm = (warp >> 2) * 64, wn = (warp & 3) * 32;

    float acc[4][4][4];
#pragma unroll
    for (int mt = 0; mt < 4; mt++)
#pragma unroll
        for (int nt = 0; nt < 4; nt++)
#pragma unroll
            for (int e = 0; e < 4; e++) acc[mt][nt][e] = 0.f;

#pragma unroll 4
    for (int kt = 0; kt < 16; kt++) {
        int k0 = kt * 8;
        float a[4][4];
#pragma unroll
        for (int mt = 0; mt < 4; mt++) {
            const float* Ar = As + (wm + mt * 16 + g) * BK_STRIDE + k0 + q;
            a[mt][0] = Ar[0];
            a[mt][2] = Ar[4];
            a[mt][1] = Ar[8 * BK_STRIDE];
            a[mt][3] = Ar[8 * BK_STRIDE + 4];
        }
#pragma unroll
        for (int nt = 0; nt < 4; nt++) {
            const float* Br = Bs + (wn + nt * 8 + g) * BK_STRIDE + k0 + q;
            float bv0 = Br[0], bv1 = Br[4];
#pragma unroll
            for (int mt = 0; mt < 4; mt++)
                mma_tf32(acc[mt][nt], a[mt][0], a[mt][1], a[mt][2], a[mt][3], bv0, bv1);
        }
    }

#pragma unroll
    for (int mt = 0; mt < 4; mt++)
#pragma unroll
        for (int nt = 0; nt < 4; nt++) {
            int mg = m0 + wm + mt * 16 + g;
            int ng = n0 + wn + nt * 8 + 2 * q;
            float bb0 = bih[ng] + bhh[ng];
            float bb1 = bih[ng + 1] + bhh[ng + 1];
            out[(size_t)mg * 512 + ng]           = acc[mt][nt][0] + bb0;
            out[(size_t)mg * 512 + ng + 1]       = acc[mt][nt][1] + bb1;
            out[(size_t)(mg + 8) * 512 + ng]     = acc[mt][nt][2] + bb0;
            out[(size_t)(mg + 8) * 512 + ng + 1] = acc[mt][nt][3] + bb1;
        }
}

// ==================== Kernel 3: recurrent phase (cluster of 4) ====================
// CTA r owns hidden units [32r,32r+32) => 128 local gate rows (i|f|g|o blocks of 32).
// Per step: acc = h @ Whh_slice^T (K=128, tf32 mma, 8 warps), add pre-gates (global),
// cell update, DSMEM broadcast of h-slice, cluster sync.
#define RC_STRIDE 132
#define R_OFF_W   0
#define R_OFF_H0  (128 * RC_STRIDE)
#define R_OFF_H1  (R_OFF_H0 + 32 * RC_STRIDE)
#define R_OFF_G   (R_OFF_H1 + 32 * RC_STRIDE)
#define R_OFF_C   (R_OFF_G  + 32 * RC_STRIDE)
#define R_FLOATS  (R_OFF_C + 32 * 33)
#define REC_SMEM_BYTES (R_FLOATS * 4)

__global__ void __launch_bounds__(256, 1) __cluster_dims__(4, 1, 1)
rec_kernel(const float* __restrict__ Whh, const float* __restrict__ pregates,
           const float* __restrict__ W1, const float* __restrict__ b1, int layer) {
    extern __shared__ float sm[];
    float* W_s  = sm + R_OFF_W;
    float* hbuf0 = sm + R_OFF_H0;
    float* hbuf1 = sm + R_OFF_H1;
    float* gates_s = sm + R_OFF_G;
    float* c_s  = sm + R_OFF_C;

    int t = threadIdx.x;
    int warp = t >> 5, lane = t & 31, g = lane >> 2, q = lane & 3;
    uint32_t r; asm("mov.u32 %0, %%cluster_ctarank;" : "=r"(r));
    int b0 = (blockIdx.x >> 2) * 32;

    { // load Whh slice: local row n -> global row (n>>5)*128 + 32r + (n&31)
        int n = t >> 1, half = (t & 1) * 16;
        int grow = (n >> 5) * HID + 32 * (int)r + (n & 31);
        const float4* wh = reinterpret_cast<const float4*>(Whh + (size_t)grow * HID) + half;
        float* dst = W_s + n * RC_STRIDE + half * 4;
#pragma unroll
        for (int k4 = 0; k4 < 16; k4++) {
            float4 w = wh[k4];
            dst[k4*4+0] = tf32r(w.x); dst[k4*4+1] = tf32r(w.y);
            dst[k4*4+2] = tf32r(w.z); dst[k4*4+3] = tf32r(w.w);
        }
    }
    for (int i = t; i < 32 * 33; i += 256) c_s[i] = 0.f;
    for (int i = t; i < 32 * RC_STRIDE; i += 256) hbuf0[i] = 0.f;
    __syncthreads();
    cluster_sync_();

    // per-thread cell-update mapping: batch m, 4 units starting at ub
    int cm = t >> 3, cub = (t & 7) * 4;
    uint32_t peer0[4], peer1[4];
    {
        uint32_t h0 = smem_u32(hbuf0), h1 = smem_u32(hbuf1);
#pragma unroll
        for (int rr = 0; rr < 4; rr++) {
            asm("mapa.shared::cluster.u32 %0, %1, %2;" : "=r"(peer0[rr]) : "r"(h0), "r"((uint32_t)rr));
            asm("mapa.shared::cluster.u32 %0, %1, %2;" : "=r"(peer1[rr]) : "r"(h1), "r"((uint32_t)rr));
        }
    }

    int cur = 0;
    for (int s = 0; s < SEQ; s++) {
        float* A = cur ? hbuf1 : hbuf0;

        // prefetch pre-gates for (cm, cub..cub+3), 4 gates
        float4 pg[4];
        {
            const float* row = pregates + ((size_t)s * BATCH + b0 + cm) * 512 + 32 * (int)r + cub;
#pragma unroll
            for (int gg = 0; gg < 4; gg++)
                pg[gg] = *reinterpret_cast<const float4*>(row + gg * 128);
        }

        // GEMM: gates[32 m][16 n per warp] += A[32][128] x W_s^T
        float acc[2][2][4];
#pragma unroll
        for (int mt = 0; mt < 2; mt++)
#pragma unroll
            for (int nt = 0; nt < 2; nt++)
#pragma unroll
                for (int e = 0; e < 4; e++) acc[mt][nt][e] = 0.f;

        const float* Wb = W_s + (warp * 16) * RC_STRIDE;
#pragma unroll 4
        for (int kt = 0; kt < 16; kt++) {
            int k0 = kt * 8;
            float a[2][4];
#pragma unroll
            for (int mt = 0; mt < 2; mt++) {
                const float* Ar = A + (mt * 16 + g) * RC_STRIDE + k0 + q;
                a[mt][0] = Ar[0];
                a[mt][2] = Ar[4];
                a[mt][1] = Ar[8 * RC_STRIDE];
                a[mt][3] = Ar[8 * RC_STRIDE + 4];
            }
#pragma unroll
            for (int nt = 0; nt < 2; nt++) {
                const float* Br = Wb + (nt * 8 + g) * RC_STRIDE + k0 + q;
                float bv0 = Br[0], bv1 = Br[4];
                mma_tf32(acc[0][nt], a[0][0], a[0][1], a[0][2], a[0][3], bv0, bv1);
                mma_tf32(acc[1][nt], a[1][0], a[1][1], a[1][2], a[1][3], bv0, bv1);
            }
        }
#pragma unroll
        for (int mt = 0; mt < 2; mt++)
#pragma unroll
            for (int nt = 0; nt < 2; nt++) {
                int n = warp * 16 + nt * 8 + 2 * q;
                int m = mt * 16 + g;
                gates_s[m * RC_STRIDE + n]           = acc[mt][nt][0];
                gates_s[m * RC_STRIDE + n + 1]       = acc[mt][nt][1];
                gates_s[(m + 8) * RC_STRIDE + n]     = acc[mt][nt][2];
                gates_s[(m + 8) * RC_STRIDE + n + 1] = acc[mt][nt][3];
            }
        __syncthreads();

        { // cell update: thread -> (cm, cub..cub+3)
            const float* gr = gates_s + cm * RC_STRIDE;
            float hv[4];
#pragma unroll
            for (int j = 0; j < 4; j++) {
                int ul = cub + j;
                float ip = gr[ul]       + ((const float*)&pg[0])[j];
                float fp = gr[32 + ul]  + ((const float*)&pg[1])[j];
                float gp = gr[64 + ul]  + ((const float*)&pg[2])[j];
                float op = gr[96 + ul]  + ((const float*)&pg[3])[j];
                float c = sigf(fp) * c_s[cm * 33 + ul] + sigf(ip) * tanh_(gp);
                c_s[cm * 33 + ul] = c;
                hv[j] = tf32r(sigf(op) * tanh_(c));
            }
            int u0 = 32 * (int)r + cub;
            uint32_t off = (uint32_t)((cm * RC_STRIDE + u0) * 4);
            uint64_t hp0 = ((uint64_t)__float_as_uint(hv[1]) << 32) | __float_as_uint(hv[0]);
            uint64_t hp1 = ((uint64_t)__float_as_uint(hv[3]) << 32) | __float_as_uint(hv[2]);
            const uint32_t* peer = cur ? peer0 : peer1;   // write NEXT buffer
#pragma unroll
            for (int rr = 0; rr < 4; rr++) {
                uint32_t base = peer[rr] + off;
                asm volatile("st.shared::cluster.b64 [%0], %1;" :: "r"(base), "l"(hp0));
                asm volatile("st.shared::cluster.b64 [%0], %1;" :: "r"(base + 8u), "l"(hp1));
            }
            if (layer == 0) {
                float4 hv4 = make_float4(hv[0], hv[1], hv[2], hv[3]);
                *reinterpret_cast<float4*>(g_ys + ((size_t)s * BATCH + b0 + cm) * HID + u0) = hv4;
            }
        }
        cluster_sync_();
        cur ^= 1;
    }

    if (layer == 1) { // fused: hidden = relu(h_last @ W1^T + b1), CTA r does rows 16r..16r+15
        float* A = cur ? hbuf1 : hbuf0;
        for (int idx = t; idx < 512; idx += 256) {
            int m = idx >> 4, jj = idx & 15;
            int row = 16 * (int)r + jj;
            const float* w = W1 + row * HID;
            const float* h = A + m * RC_STRIDE;
            float sum = b1[row];
#pragma unroll 8
            for (int k = 0; k < HID; k++) sum += w[k] * h[k];
            g_hidden[(b0 + m) * 64 + row] = fmaxf(sum, 0.f);
        }
    }
    cluster_sync_();
}

// ==================== Kernel 4: head  out[1024,NP1] = g_hidden @ W2^T + b2 ====================
#define HD_STRIDE 68
#define HEAD_SMEM_BYTES (2 * 128 * HD_STRIDE * 4)

__global__ void __launch_bounds__(256)
head_kernel(const float* __restrict__ W2, const float* __restrict__ b2,
            float* __restrict__ out) {
    extern __shared__ float sm[];
    float* As = sm;
    float* Bs = sm + 128 * HD_STRIDE;
    int t = threadIdx.x;
    int n0 = blockIdx.x * 128, m0 = blockIdx.y * 128;

    {
        const float4* src = reinterpret_cast<const float4*>(g_hidden + (size_t)m0 * 64);
#pragma unroll
        for (int ii = 0; ii < 8; ii++) {
            int i = t + ii * 256;
            float4 v = src[i];
            float* d = As + (i >> 4) * HD_STRIDE + (i & 15) * 4;
            d[0] = tf32r(v.x); d[1] = tf32r(v.y); d[2] = tf32r(v.z); d[3] = tf32r(v.w);
        }
#pragma unroll
        for (int ii = 0; ii < 8; ii++) {
            int i = t + ii * 256;
            int rn = i >> 4;
            float4 v = make_float4(0.f, 0.f, 0.f, 0.f);
            if (n0 + rn < NP1)
                v = reinterpret_cast<const float4*>(W2 + (size_t)(n0 + rn) * 64)[i & 15];
            float* d = Bs + rn * HD_STRIDE + (i & 15) * 4;
            d[0] = tf32r(v.x); d[1] = tf32r(v.y); d[2] = tf32r(v.z); d[3] = tf32r(v.w);
        }
    }
    __syncthreads();

    int warp = t >> 5, lane = t & 31, g = lane >> 2, q = lane & 3;
    int wm = (warp >> 2) * 64, wn = (warp & 3) * 32;

    float acc[4][4][4];
#pragma unroll
    for (int mt = 0; mt < 4; mt++)
#pragma unroll
        for (int nt = 0; nt < 4; nt++)
#pragma unroll
            for (int e = 0; e < 4; e++) acc[mt][nt][e] = 0.f;

#pragma unroll
    for (int kt = 0; kt < 8; kt++) {
        int k0 = kt * 8;
        float a[4][4];
#pragma unroll
        for (int mt = 0; mt < 4; mt++) {
            const float* Ar = As + (wm + mt * 16 + g) * HD_STRIDE + k0 + q;
            a[mt][0] = Ar[0];
            a[mt][2] = Ar[4];
            a[mt][1] = Ar[8 * HD_STRIDE];
            a[mt][3] = Ar[8 * HD_STRIDE + 4];
        }
#pragma unroll
        for (int nt = 0; nt < 4; nt++) {
            const float* Br = Bs + (wn + nt * 8 + g) * HD_STRIDE + k0 + q;
            float bv0 = Br[0], bv1 = Br[4];
#pragma unroll
            for (int mt = 0; mt < 4; mt++)
                mma_tf32(acc[mt][nt], a[mt][0], a[mt][1], a[mt][2], a[mt][3], bv0, bv1);
        }
    }

#pragma unroll
    for (int mt = 0; mt < 4; mt++)
#pragma unroll
        for (int nt = 0; nt < 4; nt++) {
            int mg = m0 + wm + mt * 16 + g;
            int ng = n0 + wn + nt * 8 + 2 * q;
            if (ng < NP1) {
                float bb = b2[ng];
                out[(size_t)mg * NP1 + ng]       = acc[mt][nt][0] + bb;
                out[(size_t)(mg + 8) * NP1 + ng] = acc[mt][nt][2] + bb;
            }
            if (ng + 1 < NP1) {
                float bb = b2[ng + 1];
                out[(size_t)mg * NP1 + ng + 1]       = acc[mt][nt][1] + bb;
                out[(size_t)(mg + 8) * NP1 + ng + 1] = acc[mt][nt][3] + bb;
            }
        }
}

// ==================== launch ====================
extern "C" void kernel_launch(void* const* d_in, const int* in_sizes, int n_in,
                              void* d_out, int out_size) {
    const int*   prod   = (const int*)d_in[0];
    const int*   cat    = (const int*)d_in[1];
    const float* age    = (const float*)d_in[2];
    const float* tsv    = (const float*)d_in[3];
    const float* gender = (const float*)d_in[4];
    const float* emb_p  = (const float*)d_in[5];
    const float* emb_c  = (const float*)d_in[6];
    const float* W_ts   = (const float*)d_in[7];
    const float* b_ts   = (const float*)d_in[8];
    const float* W_uf   = (const float*)d_in[9];
    const float* b_uf   = (const float*)d_in[10];
    const float* Wih0   = (const float*)d_in[11];
    const float* Whh0   = (const float*)d_in[12];
    const float* bih0   = (const float*)d_in[13];
    const float* bhh0   = (const float*)d_in[14];
    const float* Wih1   = (const float*)d_in[15];
    const float* Whh1   = (const float*)d_in[16];
    const float* bih1   = (const float*)d_in[17];
    const float* bhh1   = (const float*)d_in[18];
    const float* W1     = (const float*)d_in[19];
    const float* b1     = (const float*)d_in[20];
    const float* W2     = (const float*)d_in[21];
    const float* b2     = (const float*)d_in[22];
    float* out = (float*)d_out;

    static int configured = 0;
    cudaFuncSetAttribute(bulk_gemm_kernel, cudaFuncAttributeMaxDynamicSharedMemorySize, BULK_SMEM_BYTES);
    cudaFuncSetAttribute(rec_kernel,  cudaFuncAttributeMaxDynamicSharedMemorySize, REC_SMEM_BYTES);
    cudaFuncSetAttribute(head_kernel, cudaFuncAttributeMaxDynamicSharedMemorySize, HEAD_SMEM_BYTES);
    (void)configured;

    float* gX = nullptr;  cudaGetSymbolAddress((void**)&gX,  g_X);
    float* gG = nullptr;  cudaGetSymbolAddress((void**)&gG,  g_gates);
    float* gY = nullptr;  cudaGetSymbolAddress((void**)&gY,  g_ys);

    featurize_kernel<<<(BATCH * SEQ + 7) / 8, 256>>>(prod, cat, age, tsv, gender,
                                                     emb_p, emb_c, W_ts, b_ts, W_uf, b_uf);
    bulk_gemm_kernel<<<dim3(4, SEQ * BATCH / 128), 256, BULK_SMEM_BYTES>>>(gX, Wih0, bih0, bhh0, gG);
    rec_kernel<<<(BATCH / 32) * 4, 256, REC_SMEM_BYTES>>>(Whh0, gG, W1, b1, 0);
    bulk_gemm_kernel<<<dim3(4, SEQ * BATCH / 128), 256, BULK_SMEM_BYTES>>>(gY, Wih1, bih1, bhh1, gG);
    rec_kernel<<<(BATCH / 32) * 4, 256, REC_SMEM_BYTES>>>(Whh1, gG, W1, b1, 1);
    head_kernel<<<dim3((NP1 + 127) / 128, BATCH / 128), 256, HEAD_SMEM_BYTES>>>(W2, b2, out);
}

// round 5
// speedup vs baseline: 1.2920x; 1.1732x over previous
#include <cuda_runtime.h>
#include <cstdint>

#define NP1   100001
#define BATCH 1024
#define SEQ   50
#define LBASK 20
#define HID   128

__device__ float g_X    [SEQ * BATCH * HID];
__device__ float g_gates[SEQ * BATCH * 4 * HID];
__device__ float g_ys   [SEQ * BATCH * HID];
__device__ float g_hidden[BATCH * 64];

__device__ __forceinline__ float tf32r(float f) {
    uint32_t u; asm("cvt.rna.tf32.f32 %0, %1;" : "=r"(u) : "f"(f));
    return __uint_as_float(u);
}
__device__ __forceinline__ float sigf(float x)  { return __fdividef(1.0f, 1.0f + __expf(-x)); }
__device__ __forceinline__ float tanh_(float x) { return __fdividef(2.0f, 1.0f + __expf(-2.0f * x)) - 1.0f; }

__device__ __forceinline__ void mma_tf32(float d[4], float a0, float a1, float a2, float a3,
                                         float b0, float b1) {
    asm volatile(
        "mma.sync.aligned.m16n8k8.row.col.f32.tf32.tf32.f32 "
        "{%0,%1,%2,%3},{%4,%5,%6,%7},{%8,%9},{%0,%1,%2,%3};"
        : "+f"(d[0]), "+f"(d[1]), "+f"(d[2]), "+f"(d[3])
        : "r"(__float_as_uint(a0)), "r"(__float_as_uint(a1)),
          "r"(__float_as_uint(a2)), "r"(__float_as_uint(a3)),
          "r"(__float_as_uint(b0)), "r"(__float_as_uint(b1)));
}
__device__ __forceinline__ uint32_t smem_u32(const void* p) {
    uint32_t a;
    asm("{ .reg .u64 t; cvta.to.shared.u64 t, %1; cvt.u32.u64 %0, t; }" : "=r"(a) : "l"(p));
    return a;
}
__device__ __forceinline__ void cluster_sync_() {
    asm volatile("barrier.cluster.arrive.aligned;\n\tbarrier.cluster.wait.aligned;" ::: "memory");
}

// ==================== Kernel 1: featurize -> g_X[s][b][128] ====================
__global__ void __launch_bounds__(256)
featurize_kernel(const int* __restrict__ prod, const int* __restrict__ cat,
                 const float* __restrict__ age, const float* __restrict__ tsv,
                 const float* __restrict__ gender,
                 const float* __restrict__ emb_p, const float* __restrict__ emb_c,
                 const float* __restrict__ W_ts, const float* __restrict__ b_ts,
                 const float* __restrict__ W_uf, const float* __restrict__ b_uf) {
    int gid = blockIdx.x * 8 + (threadIdx.x >> 5);
    if (gid >= BATCH * SEQ) return;
    int lane = threadIdx.x & 31;
    int b = gid / SEQ, s = gid % SEQ;
    const int* pp = prod + gid * LBASK;
    const int* cc = cat  + gid * LBASK;
    float2 pa = make_float2(0.f, 0.f);
    float  ca = 0.f;
#pragma unroll 4
    for (int l = 0; l < LBASK; l++) {
        float2 v = *reinterpret_cast<const float2*>(emb_p + (size_t)pp[l] * 64 + lane * 2);
        pa.x += v.x; pa.y += v.y;
        ca += emb_c[cc[l] * 32 + lane];
    }
    float* xr = g_X + ((size_t)s * BATCH + b) * HID;
    pa.x *= (1.f / LBASK); pa.y *= (1.f / LBASK);
    *reinterpret_cast<float2*>(xr + lane * 2) = pa;
    xr[64 + lane] = ca * (1.f / LBASK);
    if (lane < 16) {
        xr[96 + lane] = W_ts[lane] * tsv[b * SEQ + s] + b_ts[lane];
    } else {
        int j = lane - 16;
        xr[112 + j] = W_uf[2 * j] * age[b] + W_uf[2 * j + 1] * gender[b] + b_uf[j];
    }
}

// ==================== Kernel 2: bulk ih-GEMM (64m x 128n tiles, 2 CTAs/SM) ====================
// g_gates[M][512] = X[M][128] @ Wih^T + (bih + bhh)
#define BK_STRIDE 132
#define BULK_SMEM_BYTES ((64 + 128) * BK_STRIDE * 4)

__global__ void __launch_bounds__(256)
bulk_gemm_kernel(const float* __restrict__ X, const float* __restrict__ Wih,
                 const float* __restrict__ bih, const float* __restrict__ bhh,
                 float* __restrict__ out) {
    extern __shared__ float sm[];
    float* As = sm;                      // 64 x 132
    float* Bs = sm + 64 * BK_STRIDE;     // 128 x 132
    int t = threadIdx.x;
    int n0 = blockIdx.x * 128;
    int m0 = blockIdx.y * 64;

    {
        const float4* xs = reinterpret_cast<const float4*>(X + (size_t)m0 * HID);
#pragma unroll
        for (int ii = 0; ii < 8; ii++) {
            int i = t + ii * 256;        // 2048 float4
            float4 v = xs[i];
            float* d = As + (i >> 5) * BK_STRIDE + (i & 31) * 4;
            d[0] = tf32r(v.x); d[1] = tf32r(v.y); d[2] = tf32r(v.z); d[3] = tf32r(v.w);
        }
        const float4* ws = reinterpret_cast<const float4*>(Wih + (size_t)n0 * HID);
#pragma unroll
        for (int ii = 0; ii < 16; ii++) {
            int i = t + ii * 256;        // 4096 float4
            float4 w = ws[i];
            float* e = Bs + (i >> 5) * BK_STRIDE + (i & 31) * 4;
            e[0] = tf32r(w.x); e[1] = tf32r(w.y); e[2] = tf32r(w.z); e[3] = tf32r(w.w);
        }
    }
    __syncthreads();

    int warp = t >> 5, lane = t & 31, g = lane >> 2, q = lane & 3;
    int wm = (warp >> 2) * 32, wn = (warp & 3) * 32;

    float acc[2][4][4];
#pragma unroll
    for (int mt = 0; mt < 2; mt++)
#pragma unroll
        for (int nt = 0; nt < 4; nt++)
#pragma unroll
            for (int e = 0; e < 4; e++) acc[mt][nt][e] = 0.f;

#pragma unroll 4
    for (int kt = 0; kt < 16; kt++) {
        int k0 = kt * 8;
        float a[2][4];
#pragma unroll
        for (int mt = 0; mt < 2; mt++) {
            const float* Ar = As + (wm + mt * 16 + g) * BK_STRIDE + k0 + q;
            a[mt][0] = Ar[0];
            a[mt][2] = Ar[4];
            a[mt][1] = Ar[8 * BK_STRIDE];
            a[mt][3] = Ar[8 * BK_STRIDE + 4];
        }
#pragma unroll
        for (int nt = 0; nt < 4; nt++) {
            const float* Br = Bs + (wn + nt * 8 + g) * BK_STRIDE + k0 + q;
            float bv0 = Br[0], bv1 = Br[4];
            mma_tf32(acc[0][nt], a[0][0], a[0][1], a[0][2], a[0][3], bv0, bv1);
            mma_tf32(acc[1][nt], a[1][0], a[1][1], a[1][2], a[1][3], bv0, bv1);
        }
    }

    // stage C into smem (reuse As region: 64 x 132), then coalesced float4 stores
    __syncthreads();
#pragma unroll
    for (int mt = 0; mt < 2; mt++)
#pragma unroll
        for (int nt = 0; nt < 4; nt++) {
            int mr = wm + mt * 16 + g;
            int nc = wn + nt * 8 + 2 * q;
            As[mr * BK_STRIDE + nc]           = acc[mt][nt][0];
            As[mr * BK_STRIDE + nc + 1]       = acc[mt][nt][1];
            As[(mr + 8) * BK_STRIDE + nc]     = acc[mt][nt][2];
            As[(mr + 8) * BK_STRIDE + nc + 1] = acc[mt][nt][3];
        }
    __syncthreads();
#pragma unroll
    for (int ii = 0; ii < 8; ii++) {
        int i = t + ii * 256;                // 2048 float4 = 64 x 128 floats
        int row = i >> 5, c4 = (i & 31) * 4;
        int ng = n0 + c4;
        float4 v;
        v.x = As[row * BK_STRIDE + c4]     + bih[ng]     + bhh[ng];
        v.y = As[row * BK_STRIDE + c4 + 1] + bih[ng + 1] + bhh[ng + 1];
        v.z = As[row * BK_STRIDE + c4 + 2] + bih[ng + 2] + bhh[ng + 2];
        v.w = As[row * BK_STRIDE + c4 + 3] + bih[ng + 3] + bhh[ng + 3];
        *reinterpret_cast<float4*>(out + (size_t)(m0 + row) * 512 + ng) = v;
    }
}

// ==================== Kernel 3: recurrent phase (cluster of 4, register-resident) ====================
// 512 threads/CTA, 16 warps. Warp w: m-half mt=w>>3 (rows mt*16..+16), n-group w&7 (16 gate-cols).
// Whh fragments live in 64 registers per thread for all 50 steps (loaded once from gmem).
// h buffer in fragment-major float4 layout: [kt][mt][g][q] -> (m,k),(m+8,k),(m,k+4),(m+8,k+4).
// Column permutation: within a warp's 16 cols, c=2q -> i(unit q), 2q+1 -> f, 8+2q -> g-gate, 8+2q+1 -> o.
// => each thread's accumulators are i,f,g,o for unit (w&7)*4+q, batches wm+g and wm+g+8.
__global__ void __launch_bounds__(512, 1) __cluster_dims__(4, 1, 1)
rec_kernel(const float* __restrict__ Whh, const float* __restrict__ pregates,
           const float* __restrict__ W1, const float* __restrict__ b1, int layer) {
    __shared__ float4 Abuf[2][1024];     // 2 x 16KB

    int t = threadIdx.x;
    int w = t >> 5, lane = t & 31, g = lane >> 2, q = lane & 3;
    uint32_t r; asm("mov.u32 %0, %%cluster_ctarank;" : "=r"(r));
    int b0 = (blockIdx.x >> 2) * 32;
    int ngrp = w & 7;         // n-group within warp set
    int mt   = w >> 3;        // m-half
    int wm   = mt * 16;

    // ---- load Whh fragments into registers (once) ----
    float Bf[2][16][2];
#pragma unroll
    for (int nt = 0; nt < 2; nt++) {
        // column n = ngrp*16 + nt*8 + g  ->  gate = nt*2 + (g&1), unit = 32r + ngrp*4 + (g>>1)
        int grow = (nt * 2 + (g & 1)) * 128 + 32 * (int)r + ngrp * 4 + (g >> 1);
        const float* wr = Whh + (size_t)grow * 128 + q;
#pragma unroll
        for (int kt = 0; kt < 16; kt++) {
            Bf[nt][kt][0] = tf32r(wr[kt * 8]);
            Bf[nt][kt][1] = tf32r(wr[kt * 8 + 4]);
        }
    }

    // ---- zero both h buffers ----
#pragma unroll
    for (int i = 0; i < 4; i++) {
        int idx = t + i * 512;
        Abuf[idx >> 10][idx & 1023] = make_float4(0.f, 0.f, 0.f, 0.f);
    }
    __syncthreads();
    cluster_sync_();

    // ---- per-thread ownership ----
    int u  = 32 * (int)r + ngrp * 4 + q;   // owned hidden unit
    int m0 = wm + g, m1 = wm + g + 8;      // owned batch rows
    float c0 = 0.f, c1 = 0.f;

    // DSMEM destinations for h pair (b64 at comp 0/1 or 2/3 of one float4)
    uint32_t hdst0[4], hdst1[4];
    {
        int fidx = (((u >> 3) * 2 + mt) * 8 + g) * 4 + (u & 3);
        uint32_t off = (uint32_t)(fidx * 16 + ((u >> 2) & 1) * 8);
        uint32_t a0 = smem_u32(&Abuf[0][0]) + off;
        uint32_t a1 = smem_u32(&Abuf[1][0]) + off;
#pragma unroll
        for (int rr = 0; rr < 4; rr++) {
            asm("mapa.shared::cluster.u32 %0, %1, %2;" : "=r"(hdst0[rr]) : "r"(a0), "r"((uint32_t)rr));
            asm("mapa.shared::cluster.u32 %0, %1, %2;" : "=r"(hdst1[rr]) : "r"(a1), "r"((uint32_t)rr));
        }
    }

    int cur = 0;
    for (int s = 0; s < SEQ; s++) {
        // prefetch pregates: (m0|m1, gates i,f,g,o) at column gate*128 + u
        const float* pr0 = pregates + ((size_t)s * BATCH + b0 + m0) * 512 + u;
        const float* pr1 = pregates + ((size_t)s * BATCH + b0 + m1) * 512 + u;
        float pg00 = pr0[0], pg01 = pr0[128], pg02 = pr0[256], pg03 = pr0[384];
        float pg10 = pr1[0], pg11 = pr1[128], pg12 = pr1[256], pg13 = pr1[384];

        // GEMM: acc = h @ Whh^T  (A from smem fragment layout, B from registers)
        const float4* A = Abuf[cur];
        float acc[2][4];
#pragma unroll
        for (int nt = 0; nt < 2; nt++)
#pragma unroll
            for (int e = 0; e < 4; e++) acc[nt][e] = 0.f;
#pragma unroll
        for (int kt = 0; kt < 16; kt++) {
            float4 av = A[((kt * 2 + mt) * 8 + g) * 4 + q];
            mma_tf32(acc[0], av.x, av.y, av.z, av.w, Bf[0][kt][0], Bf[0][kt][1]);
            mma_tf32(acc[1], av.x, av.y, av.z, av.w, Bf[1][kt][0], Bf[1][kt][1]);
        }

        // cell update in registers
        float c, h0v, h1v;
        c = sigf(acc[0][1] + pg01) * c0 + sigf(acc[0][0] + pg00) * tanh_(acc[1][0] + pg02);
        c0 = c;
        h0v = tf32r(sigf(acc[1][1] + pg03) * tanh_(c));
        c = sigf(acc[0][3] + pg11) * c1 + sigf(acc[0][2] + pg10) * tanh_(acc[1][2] + pg12);
        c1 = c;
        h1v = tf32r(sigf(acc[1][3] + pg13) * tanh_(c));

        // broadcast h pair to all 4 CTAs' NEXT buffer
        uint64_t hp = ((uint64_t)__float_as_uint(h1v) << 32) | __float_as_uint(h0v);
        const uint32_t* hd = cur ? hdst0 : hdst1;
#pragma unroll
        for (int rr = 0; rr < 4; rr++)
            asm volatile("st.shared::cluster.b64 [%0], %1;" :: "r"(hd[rr]), "l"(hp));

        if (layer == 0) {
            g_ys[((size_t)s * BATCH + b0 + m0) * HID + u] = h0v;
            g_ys[((size_t)s * BATCH + b0 + m1) * HID + u] = h1v;
        }
        cluster_sync_();
        cur ^= 1;
    }

    if (layer == 1) {
        // fused tail: hidden = relu(h_last @ W1^T + b1); CTA r computes rows 16r..16r+15
        const float* Af = reinterpret_cast<const float*>(&Abuf[cur][0]);
        int m = t >> 4, j = t & 15;
        int row = 16 * (int)r + j;
        const float* wrow = W1 + row * HID;
        float sum = b1[row];
        int mq = ((m >> 4) * 8 + (m & 7)) * 4;       // mt*8 + g, scaled
        int comp_m = (m >> 3) & 1;
#pragma unroll 8
        for (int uu = 0; uu < HID; uu++) {
            int fidx = ((uu >> 3) * 2) * 32 + mq + (uu & 3);
            float hval = Af[fidx * 4 + ((uu >> 2) & 1) * 2 + comp_m];
            sum += wrow[uu] * hval;
        }
        g_hidden[(b0 + m) * 64 + row] = fmaxf(sum, 0.f);
    }
    cluster_sync_();
}

// ==================== Kernel 4: head  out[1024,NP1] = g_hidden @ W2^T + b2 ====================
#define HD_STRIDE 68
#define HC_STRIDE 132
#define HEAD_SMEM_BYTES (2 * 128 * HD_STRIDE * 4)

__global__ void __launch_bounds__(256)
head_kernel(const float* __restrict__ W2, const float* __restrict__ b2,
            float* __restrict__ out) {
    extern __shared__ float sm[];
    float* As = sm;
    float* Bs = sm + 128 * HD_STRIDE;
    int t = threadIdx.x;
    int m0 = blockIdx.x * 128, n0 = blockIdx.y * 128;   // m fastest -> W2 L2-resident

    {
        const float4* src = reinterpret_cast<const float4*>(g_hidden + (size_t)m0 * 64);
#pragma unroll
        for (int ii = 0; ii < 8; ii++) {
            int i = t + ii * 256;
            float4 v = src[i];
            float* d = As + (i >> 4) * HD_STRIDE + (i & 15) * 4;
            d[0] = tf32r(v.x); d[1] = tf32r(v.y); d[2] = tf32r(v.z); d[3] = tf32r(v.w);
        }
#pragma unroll
        for (int ii = 0; ii < 8; ii++) {
            int i = t + ii * 256;
            int rn = i >> 4;
            float4 v = make_float4(0.f, 0.f, 0.f, 0.f);
            if (n0 + rn < NP1)
                v = reinterpret_cast<const float4*>(W2 + (size_t)(n0 + rn) * 64)[i & 15];
            float* d = Bs + rn * HD_STRIDE + (i & 15) * 4;
            d[0] = tf32r(v.x); d[1] = tf32r(v.y); d[2] = tf32r(v.z); d[3] = tf32r(v.w);
        }
    }
    __syncthreads();

    int warp = t >> 5, lane = t & 31, g = lane >> 2, q = lane & 3;
    int wm = (warp >> 2) * 64, wn = (warp & 3) * 32;

    float acc[4][4][4];
#pragma unroll
    for (int mt = 0; mt < 4; mt++)
#pragma unroll
        for (int nt = 0; nt < 4; nt++)
#pragma unroll
            for (int e = 0; e < 4; e++) acc[mt][nt][e] = 0.f;

#pragma unroll
    for (int kt = 0; kt < 8; kt++) {
        int k0 = kt * 8;
        float a[4][4];
#pragma unroll
        for (int mt = 0; mt < 4; mt++) {
            const float* Ar = As + (wm + mt * 16 + g) * HD_STRIDE + k0 + q;
            a[mt][0] = Ar[0];
            a[mt][2] = Ar[4];
            a[mt][1] = Ar[8 * HD_STRIDE];
            a[mt][3] = Ar[8 * HD_STRIDE + 4];
        }
#pragma unroll
        for (int nt = 0; nt < 4; nt++) {
            const float* Br = Bs + (wn + nt * 8 + g) * HD_STRIDE + k0 + q;
            float bv0 = Br[0], bv1 = Br[4];
#pragma unroll
            for (int mt = 0; mt < 4; mt++)
                mma_tf32(acc[mt][nt], a[mt][0], a[mt][1], a[mt][2], a[mt][3], bv0, bv1);
        }
    }

    // stage C tile (128x128) into smem, then fully-coalesced scalar stores
    __syncthreads();
    float* Cs = sm;                      // 128 x 132 = 67.6KB (fits in 69.6KB)
#pragma unroll
    for (int mt = 0; mt < 4; mt++)
#pragma unroll
        for (int nt = 0; nt < 4; nt++) {
            int mr = wm + mt * 16 + g;
            int nc = wn + nt * 8 + 2 * q;
            Cs[mr * HC_STRIDE + nc]           = acc[mt][nt][0];
            Cs[mr * HC_STRIDE + nc + 1]       = acc[mt][nt][1];
            Cs[(mr + 8) * HC_STRIDE + nc]     = acc[mt][nt][2];
            Cs[(mr + 8) * HC_STRIDE + nc + 1] = acc[mt][nt][3];
        }
    __syncthreads();
#pragma unroll
    for (int ii = 0; ii < 64; ii++) {
        int i = t + ii * 256;            // 16384 = 128 x 128
        int row = i >> 7, col = i & 127;
        int ng = n0 + col;
        if (ng < NP1)
            out[(size_t)(m0 + row) * NP1 + ng] = Cs[row * HC_STRIDE + col] + b2[ng];
    }
}

// ==================== launch ====================
extern "C" void kernel_launch(void* const* d_in, const int* in_sizes, int n_in,
                              void* d_out, int out_size) {
    const int*   prod   = (const int*)d_in[0];
    const int*   cat    = (const int*)d_in[1];
    const float* age    = (const float*)d_in[2];
    const float* tsv    = (const float*)d_in[3];
    const float* gender = (const float*)d_in[4];
    const float* emb_p  = (const float*)d_in[5];
    const float* emb_c  = (const float*)d_in[6];
    const float* W_ts   = (const float*)d_in[7];
    const float* b_ts   = (const float*)d_in[8];
    const float* W_uf   = (const float*)d_in[9];
    const float* b_uf   = (const float*)d_in[10];
    const float* Wih0   = (const float*)d_in[11];
    const float* Whh0   = (const float*)d_in[12];
    const float* bih0   = (const float*)d_in[13];
    const float* bhh0   = (const float*)d_in[14];
    const float* Wih1   = (const float*)d_in[15];
    const float* Whh1   = (const float*)d_in[16];
    const float* bih1   = (const float*)d_in[17];
    const float* bhh1   = (const float*)d_in[18];
    const float* W1     = (const float*)d_in[19];
    const float* b1     = (const float*)d_in[20];
    const float* W2     = (const float*)d_in[21];
    const float* b2     = (const float*)d_in[22];
    float* out = (float*)d_out;

    cudaFuncSetAttribute(bulk_gemm_kernel, cudaFuncAttributeMaxDynamicSharedMemorySize, BULK_SMEM_BYTES);
    cudaFuncSetAttribute(head_kernel, cudaFuncAttributeMaxDynamicSharedMemorySize, HEAD_SMEM_BYTES);

    float* gX = nullptr;  cudaGetSymbolAddress((void**)&gX,  g_X);
    float* gG = nullptr;  cudaGetSymbolAddress((void**)&gG,  g_gates);
    float* gY = nullptr;  cudaGetSymbolAddress((void**)&gY,  g_ys);

    featurize_kernel<<<(BATCH * SEQ + 7) / 8, 256>>>(prod, cat, age, tsv, gender,
                                                     emb_p, emb_c, W_ts, b_ts, W_uf, b_uf);
    bulk_gemm_kernel<<<dim3(4, SEQ * BATCH / 64), 256, BULK_SMEM_BYTES>>>(gX, Wih0, bih0, bhh0, gG);
    rec_kernel<<<(BATCH / 32) * 4, 512>>>(Whh0, gG, W1, b1, 0);
    bulk_gemm_kernel<<<dim3(4, SEQ * BATCH / 64), 256, BULK_SMEM_BYTES>>>(gY, Wih1, bih1, bhh1, gG);
    rec_kernel<<<(BATCH / 32) * 4, 512>>>(Whh1, gG, W1, b1, 1);
    head_kernel<<<dim3(BATCH / 128, (NP1 + 127) / 128), 256, HEAD_SMEM_BYTES>>>(W2, b2, out);
}

// round 6
// speedup vs baseline: 1.3174x; 1.0197x over previous
#include <cuda_runtime.h>
#include <cstdint>

#define NP1   100001
#define BATCH 1024
#define SEQ   50
#define LBASK 20
#define HID   128

__device__ float g_X    [SEQ * BATCH * HID];
__device__ float g_gates[SEQ * BATCH * 4 * HID];
__device__ float g_ys   [SEQ * BATCH * HID];
__device__ float g_hidden[BATCH * 64];

__device__ __forceinline__ float tf32r(float f) {
    uint32_t u; asm("cvt.rna.tf32.f32 %0, %1;" : "=r"(u) : "f"(f));
    return __uint_as_float(u);
}
__device__ __forceinline__ float sigf(float x)  { return __fdividef(1.0f, 1.0f + __expf(-x)); }
__device__ __forceinline__ float tanh_(float x) { return __fdividef(2.0f, 1.0f + __expf(-2.0f * x)) - 1.0f; }

__device__ __forceinline__ void mma_tf32(float d[4], float a0, float a1, float a2, float a3,
                                         float b0, float b1) {
    asm volatile(
        "mma.sync.aligned.m16n8k8.row.col.f32.tf32.tf32.f32 "
        "{%0,%1,%2,%3},{%4,%5,%6,%7},{%8,%9},{%0,%1,%2,%3};"
        : "+f"(d[0]), "+f"(d[1]), "+f"(d[2]), "+f"(d[3])
        : "r"(__float_as_uint(a0)), "r"(__float_as_uint(a1)),
          "r"(__float_as_uint(a2)), "r"(__float_as_uint(a3)),
          "r"(__float_as_uint(b0)), "r"(__float_as_uint(b1)));
}
__device__ __forceinline__ uint32_t smem_u32(const void* p) {
    uint32_t a;
    asm("{ .reg .u64 t; cvta.to.shared.u64 t, %1; cvt.u32.u64 %0, t; }" : "=r"(a) : "l"(p));
    return a;
}
__device__ __forceinline__ void cluster_sync_() {
    asm volatile("barrier.cluster.arrive.aligned;\n\tbarrier.cluster.wait.aligned;" ::: "memory");
}
__device__ __forceinline__ void mbar_init(uint32_t mbar, uint32_t cnt) {
    asm volatile("mbarrier.init.shared.b64 [%0], %1;" :: "r"(mbar), "r"(cnt) : "memory");
}
__device__ __forceinline__ void mbar_expect_tx(uint32_t mbar, uint32_t bytes) {
    asm volatile("mbarrier.arrive.expect_tx.shared.b64 _, [%0], %1;"
                 :: "r"(mbar), "r"(bytes) : "memory");
}
__device__ __forceinline__ void mbar_wait(uint32_t mbar, uint32_t parity) {
    asm volatile(
        "{\n\t.reg .pred P;\n\t"
        "WAIT_%=:\n\t"
        "mbarrier.try_wait.parity.acquire.cta.shared::cta.b64 P, [%0], %1, 0x989680;\n\t"
        "@!P bra WAIT_%=;\n\t}"
        :: "r"(mbar), "r"(parity) : "memory");
}
__device__ __forceinline__ void st_async_b64(uint32_t dst, uint64_t val, uint32_t rbar) {
    asm volatile("st.async.shared::cluster.mbarrier::complete_tx::bytes.b64 [%0], %1, [%2];"
                 :: "r"(dst), "l"(val), "r"(rbar) : "memory");
}

// ==================== Kernel 1: featurize -> g_X[s][b][128] ====================
__global__ void __launch_bounds__(256)
featurize_kernel(const int* __restrict__ prod, const int* __restrict__ cat,
                 const float* __restrict__ age, const float* __restrict__ tsv,
                 const float* __restrict__ gender,
                 const float* __restrict__ emb_p, const float* __restrict__ emb_c,
                 const float* __restrict__ W_ts, const float* __restrict__ b_ts,
                 const float* __restrict__ W_uf, const float* __restrict__ b_uf) {
    int gid = blockIdx.x * 8 + (threadIdx.x >> 5);
    if (gid >= BATCH * SEQ) return;
    int lane = threadIdx.x & 31;
    int b = gid / SEQ, s = gid % SEQ;
    const int* pp = prod + gid * LBASK;
    const int* cc = cat  + gid * LBASK;
    float2 pa = make_float2(0.f, 0.f);
    float  ca = 0.f;
#pragma unroll 4
    for (int l = 0; l < LBASK; l++) {
        float2 v = *reinterpret_cast<const float2*>(emb_p + (size_t)pp[l] * 64 + lane * 2);
        pa.x += v.x; pa.y += v.y;
        ca += emb_c[cc[l] * 32 + lane];
    }
    float* xr = g_X + ((size_t)s * BATCH + b) * HID;
    pa.x *= (1.f / LBASK); pa.y *= (1.f / LBASK);
    *reinterpret_cast<float2*>(xr + lane * 2) = pa;
    xr[64 + lane] = ca * (1.f / LBASK);
    if (lane < 16) {
        xr[96 + lane] = W_ts[lane] * tsv[b * SEQ + s] + b_ts[lane];
    } else {
        int j = lane - 16;
        xr[112 + j] = W_uf[2 * j] * age[b] + W_uf[2 * j + 1] * gender[b] + b_uf[j];
    }
}

// ==================== Kernel 2: bulk ih-GEMM (64m x 128n tiles) ====================
#define BK_STRIDE 132
#define BULK_SMEM_BYTES ((64 + 128) * BK_STRIDE * 4)

__global__ void __launch_bounds__(256)
bulk_gemm_kernel(const float* __restrict__ X, const float* __restrict__ Wih,
                 const float* __restrict__ bih, const float* __restrict__ bhh,
                 float* __restrict__ out) {
    extern __shared__ float sm[];
    float* As = sm;                      // 64 x 132
    float* Bs = sm + 64 * BK_STRIDE;     // 128 x 132
    int t = threadIdx.x;
    int n0 = blockIdx.x * 128;
    int m0 = blockIdx.y * 64;

    {
        const float4* xs = reinterpret_cast<const float4*>(X + (size_t)m0 * HID);
#pragma unroll
        for (int ii = 0; ii < 8; ii++) {
            int i = t + ii * 256;
            float4 v = xs[i];
            float* d = As + (i >> 5) * BK_STRIDE + (i & 31) * 4;
            d[0] = tf32r(v.x); d[1] = tf32r(v.y); d[2] = tf32r(v.z); d[3] = tf32r(v.w);
        }
        const float4* ws = reinterpret_cast<const float4*>(Wih + (size_t)n0 * HID);
#pragma unroll
        for (int ii = 0; ii < 16; ii++) {
            int i = t + ii * 256;
            float4 w = ws[i];
            float* e = Bs + (i >> 5) * BK_STRIDE + (i & 31) * 4;
            e[0] = tf32r(w.x); e[1] = tf32r(w.y); e[2] = tf32r(w.z); e[3] = tf32r(w.w);
        }
    }
    __syncthreads();

    int warp = t >> 5, lane = t & 31, g = lane >> 2, q = lane & 3;
    int wm = (warp >> 2) * 32, wn = (warp & 3) * 32;

    float acc[2][4][4];
#pragma unroll
    for (int mt = 0; mt < 2; mt++)
#pragma unroll
        for (int nt = 0; nt < 4; nt++)
#pragma unroll
            for (int e = 0; e < 4; e++) acc[mt][nt][e] = 0.f;

#pragma unroll 4
    for (int kt = 0; kt < 16; kt++) {
        int k0 = kt * 8;
        float a[2][4];
#pragma unroll
        for (int mt = 0; mt < 2; mt++) {
            const float* Ar = As + (wm + mt * 16 + g) * BK_STRIDE + k0 + q;
            a[mt][0] = Ar[0];
            a[mt][2] = Ar[4];
            a[mt][1] = Ar[8 * BK_STRIDE];
            a[mt][3] = Ar[8 * BK_STRIDE + 4];
        }
#pragma unroll
        for (int nt = 0; nt < 4; nt++) {
            const float* Br = Bs + (wn + nt * 8 + g) * BK_STRIDE + k0 + q;
            float bv0 = Br[0], bv1 = Br[4];
            mma_tf32(acc[0][nt], a[0][0], a[0][1], a[0][2], a[0][3], bv0, bv1);
            mma_tf32(acc[1][nt], a[1][0], a[1][1], a[1][2], a[1][3], bv0, bv1);
        }
    }

    __syncthreads();
#pragma unroll
    for (int mt = 0; mt < 2; mt++)
#pragma unroll
        for (int nt = 0; nt < 4; nt++) {
            int mr = wm + mt * 16 + g;
            int nc = wn + nt * 8 + 2 * q;
            As[mr * BK_STRIDE + nc]           = acc[mt][nt][0];
            As[mr * BK_STRIDE + nc + 1]       = acc[mt][nt][1];
            As[(mr + 8) * BK_STRIDE + nc]     = acc[mt][nt][2];
            As[(mr + 8) * BK_STRIDE + nc + 1] = acc[mt][nt][3];
        }
    __syncthreads();
#pragma unroll
    for (int ii = 0; ii < 8; ii++) {
        int i = t + ii * 256;
        int row = i >> 5, c4 = (i & 31) * 4;
        int ng = n0 + c4;
        float4 v;
        v.x = As[row * BK_STRIDE + c4]     + bih[ng]     + bhh[ng];
        v.y = As[row * BK_STRIDE + c4 + 1] + bih[ng + 1] + bhh[ng + 1];
        v.z = As[row * BK_STRIDE + c4 + 2] + bih[ng + 2] + bhh[ng + 2];
        v.w = As[row * BK_STRIDE + c4 + 3] + bih[ng + 3] + bhh[ng + 3];
        *reinterpret_cast<float4*>(out + (size_t)(m0 + row) * 512 + ng) = v;
    }
}

// ==================== Kernel 3: recurrent phase ====================
// Cluster of 4, CTA r owns 32 hidden units. Whh fragments register-resident.
// h-exchange via st.async + mbarrier tx-count (no cluster.sync, no L1 flush).
// Pregate loads software-pipelined one step ahead.
#define TX_BYTES 16384u

__global__ void __launch_bounds__(512, 1) __cluster_dims__(4, 1, 1)
rec_kernel(const float* __restrict__ Whh, const float* __restrict__ pregates,
           const float* __restrict__ W1, const float* __restrict__ b1, int layer) {
    __shared__ float4 Abuf[2][1024];     // 2 x 16KB, fragment-major h layout
    __shared__ __align__(8) unsigned long long mbar[2];

    int t = threadIdx.x;
    int w = t >> 5, lane = t & 31, g = lane >> 2, q = lane & 3;
    uint32_t r; asm("mov.u32 %0, %%cluster_ctarank;" : "=r"(r));
    int b0 = (blockIdx.x >> 2) * 32;
    int ngrp = w & 7;
    int mt   = w >> 3;
    int wm   = mt * 16;

    // ---- Whh fragments -> registers (once) ----
    float Bf[2][16][2];
#pragma unroll
    for (int nt = 0; nt < 2; nt++) {
        int grow = (nt * 2 + (g & 1)) * 128 + 32 * (int)r + ngrp * 4 + (g >> 1);
        const float* wr = Whh + (size_t)grow * 128 + q;
#pragma unroll
        for (int kt = 0; kt < 16; kt++) {
            Bf[nt][kt][0] = tf32r(wr[kt * 8]);
            Bf[nt][kt][1] = tf32r(wr[kt * 8 + 4]);
        }
    }

    // ---- zero both h buffers, init mbarriers ----
#pragma unroll
    for (int i = 0; i < 4; i++) {
        int idx = t + i * 512;
        Abuf[idx >> 10][idx & 1023] = make_float4(0.f, 0.f, 0.f, 0.f);
    }
    uint32_t mb0 = smem_u32(&mbar[0]);
    uint32_t mb1 = smem_u32(&mbar[1]);
    if (t == 0) {
        mbar_init(mb0, 1);
        mbar_init(mb1, 1);
        mbar_expect_tx(mb0, TX_BYTES);   // phase 0 of buf0 (stores during s=1)
        mbar_expect_tx(mb1, TX_BYTES);   // phase 0 of buf1 (stores during s=0)
    }
    __syncthreads();
    cluster_sync_();                     // peers' buffers + mbars ready

    // ---- per-thread ownership ----
    int u  = 32 * (int)r + ngrp * 4 + q;
    int m0 = wm + g, m1 = wm + g + 8;
    float c0 = 0.f, c1 = 0.f;

    // DSMEM base per rank; offsets within peer CTA's smem window are preserved
    uint32_t abase = smem_u32(&Abuf[0][0]);
    uint32_t mboff0 = mb0 - abase, mboff1 = mb1 - abase;
    uint32_t hoff;
    {
        int fidx = (((u >> 3) * 2 + mt) * 8 + g) * 4 + (u & 3);
        hoff = (uint32_t)(fidx * 16 + ((u >> 2) & 1) * 8);
    }
    uint32_t base_r[4];
#pragma unroll
    for (int rr = 0; rr < 4; rr++)
        asm("mapa.shared::cluster.u32 %0, %1, %2;" : "=r"(base_r[rr]) : "r"(abase), "r"((uint32_t)rr));

    // preload pregates for step 0
    const float* prbase0 = pregates + ((size_t)b0 + m0) * 512 + u;
    const float* prbase1 = pregates + ((size_t)b0 + m1) * 512 + u;
    float pg00 = prbase0[0], pg01 = prbase0[128], pg02 = prbase0[256], pg03 = prbase0[384];
    float pg10 = prbase1[0], pg11 = prbase1[128], pg12 = prbase1[256], pg13 = prbase1[384];

    int ph0 = 0, ph1 = 0;
    for (int s = 0; s < SEQ; s++) {
        int x = s & 1;
        if (s > 0) {
            if (x == 0) { mbar_wait(mb0, ph0); ph0 ^= 1; if (t == 0) mbar_expect_tx(mb0, TX_BYTES); }
            else        { mbar_wait(mb1, ph1); ph1 ^= 1; if (t == 0) mbar_expect_tx(mb1, TX_BYTES); }
        }

        // GEMM: acc = h @ Whh^T
        const float4* A = Abuf[x];
        float acc[2][4];
#pragma unroll
        for (int nt = 0; nt < 2; nt++)
#pragma unroll
            for (int e = 0; e < 4; e++) acc[nt][e] = 0.f;
#pragma unroll
        for (int kt = 0; kt < 16; kt++) {
            float4 av = A[((kt * 2 + mt) * 8 + g) * 4 + q];
            mma_tf32(acc[0], av.x, av.y, av.z, av.w, Bf[0][kt][0], Bf[0][kt][1]);
            mma_tf32(acc[1], av.x, av.y, av.z, av.w, Bf[1][kt][0], Bf[1][kt][1]);
        }

        // cell update in registers
        float c, h0v, h1v;
        c = sigf(acc[0][1] + pg01) * c0 + sigf(acc[0][0] + pg00) * tanh_(acc[1][0] + pg02);
        c0 = c;
        h0v = tf32r(sigf(acc[1][1] + pg03) * tanh_(c));
        c = sigf(acc[0][3] + pg11) * c1 + sigf(acc[0][2] + pg10) * tanh_(acc[1][2] + pg12);
        c1 = c;
        h1v = tf32r(sigf(acc[1][3] + pg13) * tanh_(c));

        // ship h pair to all 4 CTAs' NEXT buffer with tx-count completion
        uint64_t hp = ((uint64_t)__float_as_uint(h1v) << 32) | __float_as_uint(h0v);
        uint32_t boff = hoff + (x ? 0u : 16384u);          // target buf[x^1]
        uint32_t moff = x ? mboff0 : mboff1;
#pragma unroll
        for (int rr = 0; rr < 4; rr++)
            st_async_b64(base_r[rr] + boff, hp, base_r[rr] + moff);

        if (layer == 0) {
            g_ys[((size_t)s * BATCH + b0 + m0) * HID + u] = h0v;
            g_ys[((size_t)s * BATCH + b0 + m1) * HID + u] = h1v;
        }

        // prefetch next step's pregates (overlaps the next mbar wait + GEMM)
        if (s + 1 < SEQ) {
            const float* pr0 = prbase0 + (size_t)(s + 1) * BATCH * 512;
            const float* pr1 = prbase1 + (size_t)(s + 1) * BATCH * 512;
            pg00 = pr0[0]; pg01 = pr0[128]; pg02 = pr0[256]; pg03 = pr0[384];
            pg10 = pr1[0]; pg11 = pr1[128]; pg12 = pr1[256]; pg13 = pr1[384];
        }
    }

    if (layer == 1) {
        // final h landed in buf[0] (stores at s=49); wait phase parity ph0
        mbar_wait(mb0, ph0);
        const float* Af = reinterpret_cast<const float*>(&Abuf[0][0]);
        int m = t >> 4, j = t & 15;
        int row = 16 * (int)r + j;
        const float* wrow = W1 + row * HID;
        float sum = b1[row];
        int mq = ((m >> 4) * 8 + (m & 7)) * 4;
        int comp_m = (m >> 3) & 1;
#pragma unroll 8
        for (int uu = 0; uu < HID; uu++) {
            int fidx = ((uu >> 3) * 2) * 32 + mq + (uu & 3);
            float hval = Af[fidx * 4 + ((uu >> 2) & 1) * 2 + comp_m];
            sum += wrow[uu] * hval;
        }
        g_hidden[(b0 + m) * 64 + row] = fmaxf(sum, 0.f);
    }
    cluster_sync_();   // no CTA exits while peers' st.async may be in flight
}

// ==================== Kernel 4: head  out[1024,NP1] = g_hidden @ W2^T + b2 ====================
#define HD_STRIDE 68
#define HC_STRIDE 132
#define HEAD_SMEM_BYTES (2 * 128 * HD_STRIDE * 4)

__global__ void __launch_bounds__(256)
head_kernel(const float* __restrict__ W2, const float* __restrict__ b2,
            float* __restrict__ out) {
    extern __shared__ float sm[];
    float* As = sm;
    float* Bs = sm + 128 * HD_STRIDE;
    int t = threadIdx.x;
    int m0 = blockIdx.x * 128, n0 = blockIdx.y * 128;

    {
        const float4* src = reinterpret_cast<const float4*>(g_hidden + (size_t)m0 * 64);
#pragma unroll
        for (int ii = 0; ii < 8; ii++) {
            int i = t + ii * 256;
            float4 v = src[i];
            float* d = As + (i >> 4) * HD_STRIDE + (i & 15) * 4;
            d[0] = tf32r(v.x); d[1] = tf32r(v.y); d[2] = tf32r(v.z); d[3] = tf32r(v.w);
        }
#pragma unroll
        for (int ii = 0; ii < 8; ii++) {
            int i = t + ii * 256;
            int rn = i >> 4;
            float4 v = make_float4(0.f, 0.f, 0.f, 0.f);
            if (n0 + rn < NP1)
                v = reinterpret_cast<const float4*>(W2 + (size_t)(n0 + rn) * 64)[i & 15];
            float* d = Bs + rn * HD_STRIDE + (i & 15) * 4;
            d[0] = tf32r(v.x); d[1] = tf32r(v.y); d[2] = tf32r(v.z); d[3] = tf32r(v.w);
        }
    }
    __syncthreads();

    int warp = t >> 5, lane = t & 31, g = lane >> 2, q = lane & 3;
    int wm = (warp >> 2) * 64, wn = (warp & 3) * 32;

    float acc[4][4][4];
#pragma unroll
    for (int mt = 0; mt < 4; mt++)
#pragma unroll
        for (int nt = 0; nt < 4; nt++)
#pragma unroll
            for (int e = 0; e < 4; e++) acc[mt][nt][e] = 0.f;

#pragma unroll
    for (int kt = 0; kt < 8; kt++) {
        int k0 = kt * 8;
        float a[4][4];
#pragma unroll
        for (int mt = 0; mt < 4; mt++) {
            const float* Ar = As + (wm + mt * 16 + g) * HD_STRIDE + k0 + q;
            a[mt][0] = Ar[0];
            a[mt][2] = Ar[4];
            a[mt][1] = Ar[8 * HD_STRIDE];
            a[mt][3] = Ar[8 * HD_STRIDE + 4];
        }
#pragma unroll
        for (int nt = 0; nt < 4; nt++) {
            const float* Br = Bs + (wn + nt * 8 + g) * HD_STRIDE + k0 + q;
            float bv0 = Br[0], bv1 = Br[4];
#pragma unroll
            for (int mt = 0; mt < 4; mt++)
                mma_tf32(acc[mt][nt], a[mt][0], a[mt][1], a[mt][2], a[mt][3], bv0, bv1);
        }
    }

    __syncthreads();
    float* Cs = sm;
#pragma unroll
    for (int mt = 0; mt < 4; mt++)
#pragma unroll
        for (int nt = 0; nt < 4; nt++) {
            int mr = wm + mt * 16 + g;
            int nc = wn + nt * 8 + 2 * q;
            Cs[mr * HC_STRIDE + nc]           = acc[mt][nt][0];
            Cs[mr * HC_STRIDE + nc + 1]       = acc[mt][nt][1];
            Cs[(mr + 8) * HC_STRIDE + nc]     = acc[mt][nt][2];
            Cs[(mr + 8) * HC_STRIDE + nc + 1] = acc[mt][nt][3];
        }
    __syncthreads();
#pragma unroll
    for (int ii = 0; ii < 64; ii++) {
        int i = t + ii * 256;
        int row = i >> 7, col = i & 127;
        int ng = n0 + col;
        if (ng < NP1)
            out[(size_t)(m0 + row) * NP1 + ng] = Cs[row * HC_STRIDE + col] + b2[ng];
    }
}

// ==================== launch ====================
extern "C" void kernel_launch(void* const* d_in, const int* in_sizes, int n_in,
                              void* d_out, int out_size) {
    const int*   prod   = (const int*)d_in[0];
    const int*   cat    = (const int*)d_in[1];
    const float* age    = (const float*)d_in[2];
    const float* tsv    = (const float*)d_in[3];
    const float* gender = (const float*)d_in[4];
    const float* emb_p  = (const float*)d_in[5];
    const float* emb_c  = (const float*)d_in[6];
    const float* W_ts   = (const float*)d_in[7];
    const float* b_ts   = (const float*)d_in[8];
    const float* W_uf   = (const float*)d_in[9];
    const float* b_uf   = (const float*)d_in[10];
    const float* Wih0   = (const float*)d_in[11];
    const float* Whh0   = (const float*)d_in[12];
    const float* bih0   = (const float*)d_in[13];
    const float* bhh0   = (const float*)d_in[14];
    const float* Wih1   = (const float*)d_in[15];
    const float* Whh1   = (const float*)d_in[16];
    const float* bih1   = (const float*)d_in[17];
    const float* bhh1   = (const float*)d_in[18];
    const float* W1     = (const float*)d_in[19];
    const float* b1     = (const float*)d_in[20];
    const float* W2     = (const float*)d_in[21];
    const float* b2     = (const float*)d_in[22];
    float* out = (float*)d_out;

    cudaFuncSetAttribute(bulk_gemm_kernel, cudaFuncAttributeMaxDynamicSharedMemorySize, BULK_SMEM_BYTES);
    cudaFuncSetAttribute(head_kernel, cudaFuncAttributeMaxDynamicSharedMemorySize, HEAD_SMEM_BYTES);

    float* gX = nullptr;  cudaGetSymbolAddress((void**)&gX,  g_X);
    float* gG = nullptr;  cudaGetSymbolAddress((void**)&gG,  g_gates);
    float* gY = nullptr;  cudaGetSymbolAddress((void**)&gY,  g_ys);

    featurize_kernel<<<(BATCH * SEQ + 7) / 8, 256>>>(prod, cat, age, tsv, gender,
                                                     emb_p, emb_c, W_ts, b_ts, W_uf, b_uf);
    bulk_gemm_kernel<<<dim3(4, SEQ * BATCH / 64), 256, BULK_SMEM_BYTES>>>(gX, Wih0, bih0, bhh0, gG);
    rec_kernel<<<(BATCH / 32) * 4, 512>>>(Whh0, gG, W1, b1, 0);
    bulk_gemm_kernel<<<dim3(4, SEQ * BATCH / 64), 256, BULK_SMEM_BYTES>>>(gY, Wih1, bih1, bhh1, gG);
    rec_kernel<<<(BATCH / 32) * 4, 512>>>(Whh1, gG, W1, b1, 1);
    head_kernel<<<dim3(BATCH / 128, (NP1 + 127) / 128), 256, HEAD_SMEM_BYTES>>>(W2, b2, out);
}

// round 7
// speedup vs baseline: 1.5968x; 1.2121x over previous
#include <cuda_runtime.h>
#include <cstdint>

#define NP1   100001
#define BATCH 1024
#define SEQ   50
#define LBASK 20
#define HID   128

__device__ float g_X    [SEQ * BATCH * HID];
__device__ float g_gates[SEQ * BATCH * 4 * HID];   // layout: [s][gatecol 512][batch 1024]
__device__ float g_ys   [SEQ * BATCH * HID];
__device__ float g_hidden[BATCH * 64];

__device__ __forceinline__ float tf32r(float f) {
    uint32_t u; asm("cvt.rna.tf32.f32 %0, %1;" : "=r"(u) : "f"(f));
    return __uint_as_float(u);
}
__device__ __forceinline__ float sigf(float x)  { return __fdividef(1.0f, 1.0f + __expf(-x)); }
__device__ __forceinline__ float tanh_(float x) { return __fdividef(2.0f, 1.0f + __expf(-2.0f * x)) - 1.0f; }

__device__ __forceinline__ void mma_tf32(float d[4], float a0, float a1, float a2, float a3,
                                         float b0, float b1) {
    asm volatile(
        "mma.sync.aligned.m16n8k8.row.col.f32.tf32.tf32.f32 "
        "{%0,%1,%2,%3},{%4,%5,%6,%7},{%8,%9},{%0,%1,%2,%3};"
        : "+f"(d[0]), "+f"(d[1]), "+f"(d[2]), "+f"(d[3])
        : "r"(__float_as_uint(a0)), "r"(__float_as_uint(a1)),
          "r"(__float_as_uint(a2)), "r"(__float_as_uint(a3)),
          "r"(__float_as_uint(b0)), "r"(__float_as_uint(b1)));
}
__device__ __forceinline__ uint32_t smem_u32(const void* p) {
    uint32_t a;
    asm("{ .reg .u64 t; cvta.to.shared.u64 t, %1; cvt.u32.u64 %0, t; }" : "=r"(a) : "l"(p));
    return a;
}
__device__ __forceinline__ void cluster_sync_() {
    asm volatile("barrier.cluster.arrive.aligned;\n\tbarrier.cluster.wait.aligned;" ::: "memory");
}
__device__ __forceinline__ void mbar_init(uint32_t mbar, uint32_t cnt) {
    asm volatile("mbarrier.init.shared.b64 [%0], %1;" :: "r"(mbar), "r"(cnt) : "memory");
}
__device__ __forceinline__ void mbar_expect_tx(uint32_t mbar, uint32_t bytes) {
    asm volatile("mbarrier.arrive.expect_tx.shared.b64 _, [%0], %1;"
                 :: "r"(mbar), "r"(bytes) : "memory");
}
__device__ __forceinline__ void mbar_wait(uint32_t mbar, uint32_t parity) {
    asm volatile(
        "{\n\t.reg .pred P;\n\t"
        "WAIT_%=:\n\t"
        "mbarrier.try_wait.parity.acquire.cta.shared::cta.b64 P, [%0], %1, 0x989680;\n\t"
        "@!P bra WAIT_%=;\n\t}"
        :: "r"(mbar), "r"(parity) : "memory");
}
__device__ __forceinline__ void bulk_s2s_cluster(uint32_t dst_cluster, uint32_t src_cta,
                                                 uint32_t bytes, uint32_t mbar_cluster) {
    asm volatile(
        "cp.async.bulk.shared::cluster.shared::cta.mbarrier::complete_tx::bytes [%0], [%1], %2, [%3];"
        :: "r"(dst_cluster), "r"(src_cta), "r"(bytes), "r"(mbar_cluster) : "memory");
}

// ==================== Kernel 1: featurize -> g_X[s][b][128] ====================
__global__ void __launch_bounds__(256)
featurize_kernel(const int* __restrict__ prod, const int* __restrict__ cat,
                 const float* __restrict__ age, const float* __restrict__ tsv,
                 const float* __restrict__ gender,
                 const float* __restrict__ emb_p, const float* __restrict__ emb_c,
                 const float* __restrict__ W_ts, const float* __restrict__ b_ts,
                 const float* __restrict__ W_uf, const float* __restrict__ b_uf) {
    int gid = blockIdx.x * 8 + (threadIdx.x >> 5);
    if (gid >= BATCH * SEQ) return;
    int lane = threadIdx.x & 31;
    int b = gid / SEQ, s = gid % SEQ;
    const int* pp = prod + gid * LBASK;
    const int* cc = cat  + gid * LBASK;
    float2 pa = make_float2(0.f, 0.f);
    float  ca = 0.f;
#pragma unroll 4
    for (int l = 0; l < LBASK; l++) {
        float2 v = *reinterpret_cast<const float2*>(emb_p + (size_t)pp[l] * 64 + lane * 2);
        pa.x += v.x; pa.y += v.y;
        ca += emb_c[cc[l] * 32 + lane];
    }
    float* xr = g_X + ((size_t)s * BATCH + b) * HID;
    pa.x *= (1.f / LBASK); pa.y *= (1.f / LBASK);
    *reinterpret_cast<float2*>(xr + lane * 2) = pa;
    xr[64 + lane] = ca * (1.f / LBASK);
    if (lane < 16) {
        xr[96 + lane] = W_ts[lane] * tsv[b * SEQ + s] + b_ts[lane];
    } else {
        int j = lane - 16;
        xr[112 + j] = W_uf[2 * j] * age[b] + W_uf[2 * j + 1] * gender[b] + b_uf[j];
    }
}

// ==================== Kernel 2: bulk ih-GEMM (64m x 128n), transposed output ====================
// out[s][gatecol n][batch b] = X[s*B+b][:] . Wih[n][:] + bih[n] + bhh[n]
#define BK_STRIDE 132
#define BULK_SMEM_BYTES ((64 + 128) * BK_STRIDE * 4)

__global__ void __launch_bounds__(256)
bulk_gemm_kernel(const float* __restrict__ X, const float* __restrict__ Wih,
                 const float* __restrict__ bih, const float* __restrict__ bhh,
                 float* __restrict__ out) {
    extern __shared__ float sm[];
    float* As = sm;                      // 64 x 132
    float* Bs = sm + 64 * BK_STRIDE;     // 128 x 132
    int t = threadIdx.x;
    int n0 = blockIdx.x * 128;
    int m0 = blockIdx.y * 64;            // 64-aligned within a 1024-batch block

    {
        const float4* xs = reinterpret_cast<const float4*>(X + (size_t)m0 * HID);
#pragma unroll
        for (int ii = 0; ii < 8; ii++) {
            int i = t + ii * 256;
            float4 v = xs[i];
            float* d = As + (i >> 5) * BK_STRIDE + (i & 31) * 4;
            d[0] = tf32r(v.x); d[1] = tf32r(v.y); d[2] = tf32r(v.z); d[3] = tf32r(v.w);
        }
        const float4* ws = reinterpret_cast<const float4*>(Wih + (size_t)n0 * HID);
#pragma unroll
        for (int ii = 0; ii < 16; ii++) {
            int i = t + ii * 256;
            float4 w = ws[i];
            float* e = Bs + (i >> 5) * BK_STRIDE + (i & 31) * 4;
            e[0] = tf32r(w.x); e[1] = tf32r(w.y); e[2] = tf32r(w.z); e[3] = tf32r(w.w);
        }
    }
    __syncthreads();

    int warp = t >> 5, lane = t & 31, g = lane >> 2, q = lane & 3;
    int wm = (warp >> 2) * 32, wn = (warp & 3) * 32;

    float acc[2][4][4];
#pragma unroll
    for (int mt = 0; mt < 2; mt++)
#pragma unroll
        for (int nt = 0; nt < 4; nt++)
#pragma unroll
            for (int e = 0; e < 4; e++) acc[mt][nt][e] = 0.f;

#pragma unroll 4
    for (int kt = 0; kt < 16; kt++) {
        int k0 = kt * 8;
        float a[2][4];
#pragma unroll
        for (int mt = 0; mt < 2; mt++) {
            const float* Ar = As + (wm + mt * 16 + g) * BK_STRIDE + k0 + q;
            a[mt][0] = Ar[0];
            a[mt][2] = Ar[4];
            a[mt][1] = Ar[8 * BK_STRIDE];
            a[mt][3] = Ar[8 * BK_STRIDE + 4];
        }
#pragma unroll
        for (int nt = 0; nt < 4; nt++) {
            const float* Br = Bs + (wn + nt * 8 + g) * BK_STRIDE + k0 + q;
            float bv0 = Br[0], bv1 = Br[4];
            mma_tf32(acc[0][nt], a[0][0], a[0][1], a[0][2], a[0][3], bv0, bv1);
            mma_tf32(acc[1][nt], a[1][0], a[1][1], a[1][2], a[1][3], bv0, bv1);
        }
    }

    // stage transposed: Cs[col 0..127][m_local 0..63], stride 66 (conflict-free)
    __syncthreads();
    float* Cs = sm;                      // 128*66 = 8448 floats = As region exactly
#pragma unroll
    for (int mt = 0; mt < 2; mt++)
#pragma unroll
        for (int nt = 0; nt < 4; nt++) {
            int mr = wm + mt * 16 + g;
            int nc = wn + nt * 8 + 2 * q;
            Cs[nc * 66 + mr]           = acc[mt][nt][0];
            Cs[(nc + 1) * 66 + mr]     = acc[mt][nt][1];
            Cs[nc * 66 + mr + 8]       = acc[mt][nt][2];
            Cs[(nc + 1) * 66 + mr + 8] = acc[mt][nt][3];
        }
    __syncthreads();

    int sb = m0 >> 10;                   // sequence index
    int bb = m0 & 1023;                  // batch base
#pragma unroll
    for (int ii = 0; ii < 32; ii++) {
        int i = t + ii * 256;            // 8192 = 128 cols x 64 batch
        int col = i >> 6, bl = i & 63;
        int ng = n0 + col;
        float v = Cs[col * 66 + bl] + bih[ng] + bhh[ng];
        out[((size_t)sb * 512 + ng) * 1024 + bb + bl] = v;
    }
}

// ==================== Kernel 3: recurrent phase ====================
// Cluster of 2, batch tile 16, CTA r owns units [64r, 64r+64). Whh register-resident.
// h exchange: local STS + ONE 4KB cp.async.bulk smem->peer-smem per step (complete_tx).
#define TXB 4096u

__global__ void __launch_bounds__(512, 1) __cluster_dims__(2, 1, 1)
rec_kernel(const float* __restrict__ Whh, const float* __restrict__ pregates,
           const float* __restrict__ W1, const float* __restrict__ b1, int layer) {
    __shared__ __align__(16) float4 Abuf[2][512];   // 2 x 8KB, fragment-major h
    __shared__ __align__(8) unsigned long long mbar[2];

    int t = threadIdx.x;
    int w = t >> 5, lane = t & 31, g = lane >> 2, q = lane & 3;
    uint32_t r; asm("mov.u32 %0, %%cluster_ctarank;" : "=r"(r));
    int b0 = (blockIdx.x >> 1) * 16;

    // ---- Whh fragments -> registers. Warp w covers gate-cols [16w,16w+16) permuted:
    // col nt*8+n : gate = nt*2+(n&1), unit_local = 4w+(n>>1). Thread holds B[n=g][k=q,q+4].
    float Bf[2][16][2];
#pragma unroll
    for (int nt = 0; nt < 2; nt++) {
        int grow = (nt * 2 + (g & 1)) * 128 + 64 * (int)r + 4 * w + (g >> 1);
        const float* wr = Whh + (size_t)grow * 128 + q;
#pragma unroll
        for (int kt = 0; kt < 16; kt++) {
            Bf[nt][kt][0] = tf32r(wr[kt * 8]);
            Bf[nt][kt][1] = tf32r(wr[kt * 8 + 4]);
        }
    }

    // ---- zero buffers, init mbarriers ----
#pragma unroll
    for (int i = 0; i < 2; i++) {
        int idx = t + i * 512;
        Abuf[idx >> 9][idx & 511] = make_float4(0.f, 0.f, 0.f, 0.f);
    }
    uint32_t mb0 = smem_u32(&mbar[0]);
    uint32_t mb1 = smem_u32(&mbar[1]);
    if (t == 0) {
        mbar_init(mb0, 1); mbar_init(mb1, 1);
        mbar_expect_tx(mb0, TXB);
        mbar_expect_tx(mb1, TXB);
    }
    __syncthreads();
    cluster_sync_();

    // ---- ownership ----
    int u = 64 * (int)r + 4 * w + q;          // owned unit (acc cols 2q/2q+1 map to unit 4w+q)
    int bm0 = b0 + g, bm1 = b0 + g + 8;       // owned batch rows
    float c0 = 0.f, c1 = 0.f;

    uint32_t abase = smem_u32(&Abuf[0][0]);
    uint32_t hoff;
    {
        int fidx = ((u >> 3) * 8 + g) * 4 + (u & 3);
        hoff = (uint32_t)(fidx * 16 + ((u >> 2) & 1) * 8);
    }
    uint32_t peer = r ^ 1u;
    uint32_t pbase, pmb0, pmb1;
    asm("mapa.shared::cluster.u32 %0, %1, %2;" : "=r"(pbase) : "r"(abase), "r"(peer));
    asm("mapa.shared::cluster.u32 %0, %1, %2;" : "=r"(pmb0)  : "r"(mb0),   "r"(peer));
    asm("mapa.shared::cluster.u32 %0, %1, %2;" : "=r"(pmb1)  : "r"(mb1),   "r"(peer));
    uint32_t roff = (uint32_t)r * 4096u;      // my contiguous block within a buffer

    // pregate addressing (transposed layout [s][gate*128+u][batch])
    size_t pgi0 = (size_t)u * 1024 + bm0;
    const float* P = pregates;
    float pg00 = P[pgi0], pg01 = P[pgi0 + 131072], pg02 = P[pgi0 + 262144], pg03 = P[pgi0 + 393216];
    float pg10 = P[pgi0 + 8], pg11 = P[pgi0 + 131080], pg12 = P[pgi0 + 262152], pg13 = P[pgi0 + 393224];

    int ph0 = 0, ph1 = 0;
    for (int s = 0; s < SEQ; s++) {
        int x = s & 1;
        if (s > 0) {
            if (x == 0) { mbar_wait(mb0, ph0); ph0 ^= 1; if (t == 0) mbar_expect_tx(mb0, TXB); }
            else        { mbar_wait(mb1, ph1); ph1 ^= 1; if (t == 0) mbar_expect_tx(mb1, TXB); }
        }

        // GEMM: acc = h @ Whh^T  (A fragment-major in smem, B in registers)
        const float4* A = Abuf[x];
        float acc[2][4];
#pragma unroll
        for (int nt = 0; nt < 2; nt++)
#pragma unroll
            for (int e = 0; e < 4; e++) acc[nt][e] = 0.f;
#pragma unroll
        for (int kt = 0; kt < 16; kt++) {
            float4 av = A[(kt * 8 + g) * 4 + q];
            mma_tf32(acc[0], av.x, av.y, av.z, av.w, Bf[0][kt][0], Bf[0][kt][1]);
            mma_tf32(acc[1], av.x, av.y, av.z, av.w, Bf[1][kt][0], Bf[1][kt][1]);
        }

        // cell update in registers (acc[0]=i/f, acc[1]=g/o; e 0,1 = batch bm0; e 2,3 = bm1)
        float c, h0v, h1v;
        c = sigf(acc[0][1] + pg01) * c0 + sigf(acc[0][0] + pg00) * tanh_(acc[1][0] + pg02);
        c0 = c;
        h0v = tf32r(sigf(acc[1][1] + pg03) * tanh_(c));
        c = sigf(acc[0][3] + pg11) * c1 + sigf(acc[0][2] + pg10) * tanh_(acc[1][2] + pg12);
        c1 = c;
        h1v = tf32r(sigf(acc[1][3] + pg13) * tanh_(c));

        // local STS of h pair into NEXT buffer (own region)
        uint64_t hp = ((uint64_t)__float_as_uint(h1v) << 32) | __float_as_uint(h0v);
        uint32_t la = abase + (uint32_t)(x ^ 1) * 8192u + hoff;
        asm volatile("st.shared.b64 [%0], %1;" :: "r"(la), "l"(hp) : "memory");

        if (layer == 0) {
            g_ys[((size_t)s * BATCH + bm0) * HID + u] = h0v;
            g_ys[((size_t)s * BATCH + bm1) * HID + u] = h1v;
        }
        __syncthreads();
        asm volatile("fence.proxy.async.shared::cta;" ::: "memory");

        if (t == 0) {   // ONE 4KB bulk copy to peer's next buffer, tx on peer's mbar
            uint32_t src = abase + (uint32_t)(x ^ 1) * 8192u + roff;
            uint32_t dst = pbase + (uint32_t)(x ^ 1) * 8192u + roff;
            uint32_t mbp = x ? pmb0 : pmb1;
            bulk_s2s_cluster(dst, src, TXB, mbp);
        }

        if (s + 1 < SEQ) {   // prefetch next pregates (overlaps next wait + GEMM)
            const float* Pn = pregates + (size_t)(s + 1) * 524288;
            pg00 = Pn[pgi0]; pg01 = Pn[pgi0 + 131072]; pg02 = Pn[pgi0 + 262144]; pg03 = Pn[pgi0 + 393216];
            pg10 = Pn[pgi0 + 8]; pg11 = Pn[pgi0 + 131080]; pg12 = Pn[pgi0 + 262152]; pg13 = Pn[pgi0 + 393224];
        }
    }

    // consume final arrival (s=49 wrote buffer 0 / mbar0)
    mbar_wait(mb0, ph0);

    if (layer == 1) {
        // fused tail: hidden = relu(h_last @ W1^T + b1); CTA r -> rows [32r, 32r+32)
        const float* Af = reinterpret_cast<const float*>(&Abuf[0][0]);
        int m = t >> 5, j = t & 31;
        int row = 32 * (int)r + j;
        const float* wrow = W1 + row * HID;
        float sum = b1[row];
#pragma unroll 8
        for (int uu = 0; uu < HID; uu++) {
            int fi = (((uu >> 3) * 8 + (m & 7)) * 4 + (uu & 3)) * 4 + ((uu >> 2) & 1) * 2 + (m >> 3);
            sum += wrow[uu] * Af[fi];
        }
        g_hidden[(b0 + m) * 64 + row] = fmaxf(sum, 0.f);
    }
    cluster_sync_();
}

// ==================== Kernel 4: head  out[1024,NP1] = g_hidden @ W2^T + b2 ====================
#define HD_STRIDE 68
#define HC_STRIDE 132
#define HEAD_SMEM_BYTES (2 * 128 * HD_STRIDE * 4)

__global__ void __launch_bounds__(256)
head_kernel(const float* __restrict__ W2, const float* __restrict__ b2,
            float* __restrict__ out) {
    extern __shared__ float sm[];
    float* As = sm;
    float* Bs = sm + 128 * HD_STRIDE;
    int t = threadIdx.x;
    int m0 = blockIdx.x * 128, n0 = blockIdx.y * 128;

    {
        const float4* src = reinterpret_cast<const float4*>(g_hidden + (size_t)m0 * 64);
#pragma unroll
        for (int ii = 0; ii < 8; ii++) {
            int i = t + ii * 256;
            float4 v = src[i];
            float* d = As + (i >> 4) * HD_STRIDE + (i & 15) * 4;
            d[0] = tf32r(v.x); d[1] = tf32r(v.y); d[2] = tf32r(v.z); d[3] = tf32r(v.w);
        }
#pragma unroll
        for (int ii = 0; ii < 8; ii++) {
            int i = t + ii * 256;
            int rn = i >> 4;
            float4 v = make_float4(0.f, 0.f, 0.f, 0.f);
            if (n0 + rn < NP1)
                v = reinterpret_cast<const float4*>(W2 + (size_t)(n0 + rn) * 64)[i & 15];
            float* d = Bs + rn * HD_STRIDE + (i & 15) * 4;
            d[0] = tf32r(v.x); d[1] = tf32r(v.y); d[2] = tf32r(v.z); d[3] = tf32r(v.w);
        }
    }
    __syncthreads();

    int warp = t >> 5, lane = t & 31, g = lane >> 2, q = lane & 3;
    int wm = (warp >> 2) * 64, wn = (warp & 3) * 32;

    float acc[4][4][4];
#pragma unroll
    for (int mt = 0; mt < 4; mt++)
#pragma unroll
        for (int nt = 0; nt < 4; nt++)
#pragma unroll
            for (int e = 0; e < 4; e++) acc[mt][nt][e] = 0.f;

#pragma unroll
    for (int kt = 0; kt < 8; kt++) {
        int k0 = kt * 8;
        float a[4][4];
#pragma unroll
        for (int mt = 0; mt < 4; mt++) {
            const float* Ar = As + (wm + mt * 16 + g) * HD_STRIDE + k0 + q;
            a[mt][0] = Ar[0];
            a[mt][2] = Ar[4];
            a[mt][1] = Ar[8 * HD_STRIDE];
            a[mt][3] = Ar[8 * HD_STRIDE + 4];
        }
#pragma unroll
        for (int nt = 0; nt < 4; nt++) {
            const float* Br = Bs + (wn + nt * 8 + g) * HD_STRIDE + k0 + q;
            float bv0 = Br[0], bv1 = Br[4];
#pragma unroll
            for (int mt = 0; mt < 4; mt++)
                mma_tf32(acc[mt][nt], a[mt][0], a[mt][1], a[mt][2], a[mt][3], bv0, bv1);
        }
    }

    __syncthreads();
    float* Cs = sm;
#pragma unroll
    for (int mt = 0; mt < 4; mt++)
#pragma unroll
        for (int nt = 0; nt < 4; nt++) {
            int mr = wm + mt * 16 + g;
            int nc = wn + nt * 8 + 2 * q;
            Cs[mr * HC_STRIDE + nc]           = acc[mt][nt][0];
            Cs[mr * HC_STRIDE + nc + 1]       = acc[mt][nt][1];
            Cs[(mr + 8) * HC_STRIDE + nc]     = acc[mt][nt][2];
            Cs[(mr + 8) * HC_STRIDE + nc + 1] = acc[mt][nt][3];
        }
    __syncthreads();
#pragma unroll
    for (int ii = 0; ii < 64; ii++) {
        int i = t + ii * 256;
        int row = i >> 7, col = i & 127;
        int ng = n0 + col;
        if (ng < NP1)
            out[(size_t)(m0 + row) * NP1 + ng] = Cs[row * HC_STRIDE + col] + b2[ng];
    }
}

// ==================== launch ====================
extern "C" void kernel_launch(void* const* d_in, const int* in_sizes, int n_in,
                              void* d_out, int out_size) {
    const int*   prod   = (const int*)d_in[0];
    const int*   cat    = (const int*)d_in[1];
    const float* age    = (const float*)d_in[2];
    const float* tsv    = (const float*)d_in[3];
    const float* gender = (const float*)d_in[4];
    const float* emb_p  = (const float*)d_in[5];
    const float* emb_c  = (const float*)d_in[6];
    const float* W_ts   = (const float*)d_in[7];
    const float* b_ts   = (const float*)d_in[8];
    const float* W_uf   = (const float*)d_in[9];
    const float* b_uf   = (const float*)d_in[10];
    const float* Wih0   = (const float*)d_in[11];
    const float* Whh0   = (const float*)d_in[12];
    const float* bih0   = (const float*)d_in[13];
    const float* bhh0   = (const float*)d_in[14];
    const float* Wih1   = (const float*)d_in[15];
    const float* Whh1   = (const float*)d_in[16];
    const float* bih1   = (const float*)d_in[17];
    const float* bhh1   = (const float*)d_in[18];
    const float* W1     = (const float*)d_in[19];
    const float* b1     = (const float*)d_in[20];
    const float* W2     = (const float*)d_in[21];
    const float* b2     = (const float*)d_in[22];
    float* out = (float*)d_out;

    cudaFuncSetAttribute(bulk_gemm_kernel, cudaFuncAttributeMaxDynamicSharedMemorySize, BULK_SMEM_BYTES);
    cudaFuncSetAttribute(head_kernel, cudaFuncAttributeMaxDynamicSharedMemorySize, HEAD_SMEM_BYTES);

    float* gX = nullptr;  cudaGetSymbolAddress((void**)&gX,  g_X);
    float* gG = nullptr;  cudaGetSymbolAddress((void**)&gG,  g_gates);
    float* gY = nullptr;  cudaGetSymbolAddress((void**)&gY,  g_ys);

    featurize_kernel<<<(BATCH * SEQ + 7) / 8, 256>>>(prod, cat, age, tsv, gender,
                                                     emb_p, emb_c, W_ts, b_ts, W_uf, b_uf);
    bulk_gemm_kernel<<<dim3(4, SEQ * BATCH / 64), 256, BULK_SMEM_BYTES>>>(gX, Wih0, bih0, bhh0, gG);
    rec_kernel<<<(BATCH / 16) * 2, 512>>>(Whh0, gG, W1, b1, 0);
    bulk_gemm_kernel<<<dim3(4, SEQ * BATCH / 64), 256, BULK_SMEM_BYTES>>>(gY, Wih1, bih1, bhh1, gG);
    rec_kernel<<<(BATCH / 16) * 2, 512>>>(Whh1, gG, W1, b1, 1);
    head_kernel<<<dim3(BATCH / 128, (NP1 + 127) / 128), 256, HEAD_SMEM_BYTES>>>(W2, b2, out);
}